// round 13
// baseline (speedup 1.0000x reference)
#include <cuda_runtime.h>
#include <cuda_fp16.h>
#include <stdint.h>
#include <math.h>

#define BATCH 64
#define SEQ   197
#define DMODEL 768
#define NBLK  12
#define NHEAD 12
#define DHEAD 64
#define FFDIM 3072
#define NOUT  1000
#define NTOK  196
#define M_ALL (BATCH*SEQ)   // 12608
#define M_PAT (BATCH*NTOK)  // 12544
#define MPAD  12800
#define MTILES 99           // ceil(12608/128)

// ---- scratch ----
__device__ __align__(16) __half g_patch_h[(size_t)M_PAT * DMODEL];
__device__ float  g_tok   [(size_t)M_PAT * DMODEL];
__device__ float  g_x     [(size_t)M_ALL * DMODEL];
__device__ __align__(16) __half g_h_h [(size_t)MPAD * DMODEL];
__device__ __align__(16) __half g_qkv_h[(size_t)M_ALL * 3 * DMODEL];
__device__ __align__(16) __half g_y_h [(size_t)MPAD * DMODEL];
__device__ __align__(16) __half g_ff_h[(size_t)MPAD * FFDIM];
__device__ float  g_logits[BATCH * NOUT];
__device__ __align__(16) __half g_wmap_t[(size_t)DMODEL * DMODEL];
__device__ __align__(16) __half g_wqkv_t[(size_t)NBLK * 3 * DMODEL * DMODEL];
__device__ __align__(16) __half g_wo_t  [(size_t)NBLK * DMODEL * DMODEL];
__device__ __align__(16) __half g_wm1_t [(size_t)NBLK * FFDIM * DMODEL];
__device__ __align__(16) __half g_wm2_t [(size_t)NBLK * DMODEL * FFDIM];

__device__ __forceinline__ void cpasync16(uint32_t s, const void* g) {
    asm volatile("cp.async.cg.shared.global [%0], [%1], 16;" :: "r"(s), "l"(g));
}
__device__ __forceinline__ uint32_t smem_u32(const void* p) {
    uint32_t a;
    asm("{ .reg .u64 t; cvta.to.shared.u64 t, %1; cvt.u32.u64 %0, t; }" : "=r"(a) : "l"(p));
    return a;
}
#define CP_COMMIT() asm volatile("cp.async.commit_group;" ::: "memory")
#define CP_WAIT2()  asm volatile("cp.async.wait_group 2;" ::: "memory")
#define CP_WAIT1()  asm volatile("cp.async.wait_group 1;" ::: "memory")
#define CP_WAIT0()  asm volatile("cp.async.wait_group 0;" ::: "memory")

#define LDSM_X4(r0,r1,r2,r3,addr) \
    asm volatile("ldmatrix.sync.aligned.m8n8.x4.shared.b16 {%0,%1,%2,%3}, [%4];" \
                 : "=r"(r0), "=r"(r1), "=r"(r2), "=r"(r3) : "r"(addr))
#define LDSM_X2(r0,r1,addr) \
    asm volatile("ldmatrix.sync.aligned.m8n8.x2.shared.b16 {%0,%1}, [%2];" \
                 : "=r"(r0), "=r"(r1) : "r"(addr))

__device__ __forceinline__ void mma_f16f32(float& c0, float& c1, float& c2, float& c3,
                                           uint32_t a0, uint32_t a1, uint32_t a2, uint32_t a3,
                                           uint32_t b0, uint32_t b1) {
    asm volatile("mma.sync.aligned.m16n8k16.row.col.f32.f16.f16.f32 "
                 "{%0,%1,%2,%3}, {%4,%5,%6,%7}, {%8,%9}, {%0,%1,%2,%3};"
                 : "+f"(c0), "+f"(c1), "+f"(c2), "+f"(c3)
                 : "r"(a0), "r"(a1), "r"(a2), "r"(a3), "r"(b0), "r"(b1));
}

// exact tanh-GELU via sigmoid identity: 0.5u(1+tanh(g)) = u * sigmoid(2g)
__device__ __forceinline__ float gelu_fast(float u) {
    float t = 1.5957691216057308f * (u + 0.044715f * u * u * u);
    return u / (1.0f + __expf(-t));
}

// ---- HMMA GEMM, f32 acc, ldmatrix fragments (A x4, B x2), 3-stage cp.async ----
#define LDK 72
#define STAGE_E (128 * LDK)
#define GEMM_SMEM (6 * STAGE_E * 2)   // 110592 B

__global__ __launch_bounds__(256, 2) void mma_gemm_kernel(
    const __half* __restrict__ A, const __half* __restrict__ Bw,
    const float* __restrict__ bias, const float* __restrict__ res,
    float* __restrict__ outF, __half* __restrict__ outS,
    int Mreal, int N, int K, int act)
{
    extern __shared__ __half smem[];
    int tid = threadIdx.x;
    int wid = tid >> 5, lane = tid & 31;
    int warpM = wid & 1, warpN = wid >> 1;
    int gid = lane >> 2, tig = lane & 3;
    int mT = blockIdx.y * 128, nT = blockIdx.x * 128;
    const int C = K / 64;

    const __half* Ab = A + (size_t)mT * K;
    const __half* Bb = Bw + (size_t)nT * K;
    uint32_t sbase = smem_u32(smem);

    int ldrow[4], ldseg[4];
#pragma unroll
    for (int i = 0; i < 4; i++) {
        int c = tid + i * 256;
        ldrow[i] = c >> 3;
        ldseg[i] = c & 7;
    }

    auto load_chunk = [&](int c) {
        int s = c % 3;
        int kOff = c * 64;
        uint32_t sA = sbase + s * (2 * STAGE_E * 2);
        uint32_t sB = sA + STAGE_E * 2;
#pragma unroll
        for (int i = 0; i < 4; i++) {
            int r = ldrow[i], sg = ldseg[i];
            cpasync16(sA + (r * LDK + sg * 8) * 2, Ab + (size_t)r * K + kOff + sg * 8);
            cpasync16(sB + (r * LDK + sg * 8) * 2, Bb + (size_t)r * K + kOff + sg * 8);
        }
        CP_COMMIT();
    };

    float acc[4][4][4];
#pragma unroll
    for (int i = 0; i < 4; i++)
#pragma unroll
        for (int j = 0; j < 4; j++)
#pragma unroll
            for (int k = 0; k < 4; k++) acc[i][j][k] = 0.0f;

    load_chunk(0);
    if (C > 1) load_chunk(1);
    if (C > 2) load_chunk(2);

    int lr = lane & 7;
    uint32_t aRow = (uint32_t)(warpM * 64 + lr + ((lane >> 3) & 1) * 8);
    uint32_t aCol = (uint32_t)(((lane >> 4) & 1) * 8);
    uint32_t bRow = (uint32_t)(warpN * 32 + lr);
    uint32_t bCol = (uint32_t)(((lane >> 3) & 1) * 8);

    for (int c = 0; c < C; c++) {
        int rem = C - 1 - c;
        if (rem >= 2) CP_WAIT2(); else if (rem == 1) CP_WAIT1(); else CP_WAIT0();
        __syncthreads();
        uint32_t sAaddr = sbase + (c % 3) * (2 * STAGE_E * 2);
        uint32_t sBaddr = sAaddr + STAGE_E * 2;
#pragma unroll
        for (int ks = 0; ks < 4; ks++) {
            uint32_t kk0 = ks * 16;
            uint32_t a[4][4], b[4][2];
#pragma unroll
            for (int mt = 0; mt < 4; mt++)
                LDSM_X4(a[mt][0], a[mt][1], a[mt][2], a[mt][3],
                        sAaddr + ((aRow + mt * 16) * LDK + kk0 + aCol) * 2);
#pragma unroll
            for (int nt = 0; nt < 4; nt++)
                LDSM_X2(b[nt][0], b[nt][1],
                        sBaddr + ((bRow + nt * 8) * LDK + kk0 + bCol) * 2);
#pragma unroll
            for (int mt = 0; mt < 4; mt++)
#pragma unroll
                for (int nt = 0; nt < 4; nt++)
                    mma_f16f32(acc[mt][nt][0], acc[mt][nt][1], acc[mt][nt][2], acc[mt][nt][3],
                               a[mt][0], a[mt][1], a[mt][2], a[mt][3], b[nt][0], b[nt][1]);
        }
        __syncthreads();
        if (c + 3 < C) load_chunk(c + 3);
    }

#pragma unroll
    for (int mt = 0; mt < 4; mt++) {
#pragma unroll
        for (int half_ = 0; half_ < 2; half_++) {
            int row = mT + warpM * 64 + mt * 16 + gid + half_ * 8;
            if (row >= Mreal) continue;
#pragma unroll
            for (int nt = 0; nt < 4; nt++) {
                int col = nT + warpN * 32 + nt * 8 + tig * 2;
                float v0 = acc[mt][nt][half_ * 2 + 0];
                float v1 = acc[mt][nt][half_ * 2 + 1];
                float2 bb = *(const float2*)(bias + col);
                v0 += bb.x; v1 += bb.y;
                if (act == 1) { v0 = gelu_fast(v0); v1 = gelu_fast(v1); }
                if (res) {
                    float2 rr = *(const float2*)(res + (size_t)row * N + col);
                    v0 += rr.x; v1 += rr.y;
                }
                if (outF) *(float2*)(outF + (size_t)row * N + col) = make_float2(v0, v1);
                if (outS) {
                    union { __half h[2]; uint32_t u; } P;
                    P.h[0] = __float2half_rn(v0);
                    P.h[1] = __float2half_rn(v1);
                    *(uint32_t*)(outS + (size_t)row * N + col) = P.u;
                }
            }
        }
    }
}

// ---- tensor-core attention, register softmax, 2 CTA/SM ----
#define SP 224
#define LDQK 72
#define LDV 232
#define ATTN_SMEM ((64*LDQK + SP*LDQK + 64*LDV + 64*LDV) * 2 + 2 * 64 * 4 * 4)

__global__ __launch_bounds__(256, 2) void attn_kernel(const __half* __restrict__ qkv,
                                                      __half* __restrict__ yH) {
    extern __shared__ char smc[];
    __half* Qs = (__half*)smc;
    __half* Ks = Qs + 64 * LDQK;
    __half* Vt = Ks + SP * LDQK;
    __half* Pm = Vt + 64 * LDV;
    float*  redA = (float*)(Pm + 64 * LDV);
    float*  redB = redA + 64 * 4;

    int h = blockIdx.x, b = blockIdx.y;
    int tid = threadIdx.x, wid = tid >> 5, lane = tid & 31;
    int gid = lane >> 2, tig = lane & 3;
    int wm = wid >> 2, wn = wid & 3;

    const __half* base = qkv + (size_t)(b * SEQ) * (3 * DMODEL) + h * DHEAD;

    for (int idx = tid; idx < SP * 32; idx += 256) {
        int t = idx >> 5, p = idx & 31;
        uint32_t kv = 0;
        if (t < SEQ) kv = *(const uint32_t*)(base + (size_t)t * (3 * DMODEL) + DMODEL + 2 * p);
        *(uint32_t*)(Ks + t * LDQK + 2 * p) = kv;
    }
    for (int idx = tid; idx < SP * 16; idx += 256) {
        int t = idx >> 4, dq = idx & 15;
        int d = dq * 4;
        __half v[4] = {__float2half(0.f), __float2half(0.f), __float2half(0.f), __float2half(0.f)};
        if (t < SEQ) *(uint2*)v = *(const uint2*)(base + (size_t)t * (3 * DMODEL) + 2 * DMODEL + d);
        Vt[(d + 0) * LDV + t] = v[0];
        Vt[(d + 1) * LDV + t] = v[1];
        Vt[(d + 2) * LDV + t] = v[2];
        Vt[(d + 3) * LDV + t] = v[3];
    }
    __syncthreads();

    for (int q0 = 0; q0 < SP; q0 += 64) {
        for (int idx = tid; idx < 64 * 32; idx += 256) {
            int rl = idx >> 5, p = idx & 31;
            int t = q0 + rl;
            uint32_t qv = 0;
            if (t < SEQ) {
                __half2 q2 = *(const __half2*)(base + (size_t)t * (3 * DMODEL) + 2 * p);
                float2 qf = __half22float2(q2);
                __half2 qs = __floats2half2_rn(qf.x * 0.125f, qf.y * 0.125f);
                qv = *(uint32_t*)&qs;
            }
            *(uint32_t*)(Qs + rl * LDQK + 2 * p) = qv;
        }
        __syncthreads();

        float c[2][7][4];
#pragma unroll
        for (int mi = 0; mi < 2; mi++)
#pragma unroll
            for (int ni = 0; ni < 7; ni++)
#pragma unroll
                for (int k = 0; k < 4; k++) c[mi][ni][k] = 0.0f;
#pragma unroll
        for (int ks = 0; ks < 4; ks++) {
            int kk = ks * 16 + tig * 2;
            uint32_t a[2][4], bf[7][2];
#pragma unroll
            for (int mi = 0; mi < 2; mi++) {
                const __half* ap = Qs + (wm * 32 + mi * 16 + gid) * LDQK + kk;
                a[mi][0] = *(const uint32_t*)(ap);
                a[mi][1] = *(const uint32_t*)(ap + 8 * LDQK);
                a[mi][2] = *(const uint32_t*)(ap + 8);
                a[mi][3] = *(const uint32_t*)(ap + 8 * LDQK + 8);
            }
#pragma unroll
            for (int ni = 0; ni < 7; ni++) {
                const __half* bp = Ks + (wn * 56 + ni * 8 + gid) * LDQK + kk;
                bf[ni][0] = *(const uint32_t*)(bp);
                bf[ni][1] = *(const uint32_t*)(bp + 8);
            }
#pragma unroll
            for (int mi = 0; mi < 2; mi++)
#pragma unroll
                for (int ni = 0; ni < 7; ni++)
                    mma_f16f32(c[mi][ni][0], c[mi][ni][1], c[mi][ni][2], c[mi][ni][3],
                               a[mi][0], a[mi][1], a[mi][2], a[mi][3], bf[ni][0], bf[ni][1]);
        }

#pragma unroll
        for (int ni = 0; ni < 7; ni++) {
            int col = wn * 56 + ni * 8 + 2 * tig;
            if (col >= SEQ) { c[0][ni][0] = c[0][ni][2] = c[1][ni][0] = c[1][ni][2] = -1e30f; }
            if (col + 1 >= SEQ) { c[0][ni][1] = c[0][ni][3] = c[1][ni][1] = c[1][ni][3] = -1e30f; }
        }

#pragma unroll
        for (int mi = 0; mi < 2; mi++) {
            float m0 = -1e30f, m1 = -1e30f;
#pragma unroll
            for (int ni = 0; ni < 7; ni++) {
                m0 = fmaxf(m0, fmaxf(c[mi][ni][0], c[mi][ni][1]));
                m1 = fmaxf(m1, fmaxf(c[mi][ni][2], c[mi][ni][3]));
            }
#pragma unroll
            for (int o = 1; o <= 2; o <<= 1) {
                m0 = fmaxf(m0, __shfl_xor_sync(0xffffffffu, m0, o));
                m1 = fmaxf(m1, __shfl_xor_sync(0xffffffffu, m1, o));
            }
            if (tig == 0) {
                int rr = wm * 32 + mi * 16 + gid;
                redA[rr * 4 + wn] = m0;
                redA[(rr + 8) * 4 + wn] = m1;
            }
        }
        __syncthreads();

#pragma unroll
        for (int mi = 0; mi < 2; mi++) {
            int rr = wm * 32 + mi * 16 + gid;
            float4 ra = *(const float4*)(redA + rr * 4);
            float4 rb = *(const float4*)(redA + (rr + 8) * 4);
            float m0 = fmaxf(fmaxf(ra.x, ra.y), fmaxf(ra.z, ra.w));
            float m1 = fmaxf(fmaxf(rb.x, rb.y), fmaxf(rb.z, rb.w));
            float s0 = 0.0f, s1 = 0.0f;
#pragma unroll
            for (int ni = 0; ni < 7; ni++) {
                float e0 = __expf(c[mi][ni][0] - m0);
                float e1 = __expf(c[mi][ni][1] - m0);
                float e2 = __expf(c[mi][ni][2] - m1);
                float e3 = __expf(c[mi][ni][3] - m1);
                c[mi][ni][0] = e0; c[mi][ni][1] = e1; c[mi][ni][2] = e2; c[mi][ni][3] = e3;
                s0 += e0 + e1; s1 += e2 + e3;
            }
#pragma unroll
            for (int o = 1; o <= 2; o <<= 1) {
                s0 += __shfl_xor_sync(0xffffffffu, s0, o);
                s1 += __shfl_xor_sync(0xffffffffu, s1, o);
            }
            if (tig == 0) {
                redB[rr * 4 + wn] = s0;
                redB[(rr + 8) * 4 + wn] = s1;
            }
        }
        __syncthreads();

#pragma unroll
        for (int mi = 0; mi < 2; mi++) {
            int rr = wm * 32 + mi * 16 + gid;
            float4 ra = *(const float4*)(redB + rr * 4);
            float4 rb = *(const float4*)(redB + (rr + 8) * 4);
            float i0 = 1.0f / (ra.x + ra.y + ra.z + ra.w);
            float i1 = 1.0f / (rb.x + rb.y + rb.z + rb.w);
#pragma unroll
            for (int ni = 0; ni < 7; ni++) {
                int col = wn * 56 + ni * 8 + 2 * tig;
                __half2 p0 = __floats2half2_rn(c[mi][ni][0] * i0, c[mi][ni][1] * i0);
                __half2 p1 = __floats2half2_rn(c[mi][ni][2] * i1, c[mi][ni][3] * i1);
                *(__half2*)(Pm + rr * LDV + col) = p0;
                *(__half2*)(Pm + (rr + 8) * LDV + col) = p1;
            }
        }
        __syncthreads();

        float o[2][2][4];
#pragma unroll
        for (int mi = 0; mi < 2; mi++)
#pragma unroll
            for (int ni = 0; ni < 2; ni++)
#pragma unroll
                for (int k = 0; k < 4; k++) o[mi][ni][k] = 0.0f;
#pragma unroll
        for (int ks = 0; ks < 14; ks++) {
            int kk = ks * 16 + tig * 2;
            uint32_t a[2][4], bf[2][2];
#pragma unroll
            for (int mi = 0; mi < 2; mi++) {
                const __half* ap = Pm + (wm * 32 + mi * 16 + gid) * LDV + kk;
                a[mi][0] = *(const uint32_t*)(ap);
                a[mi][1] = *(const uint32_t*)(ap + 8 * LDV);
                a[mi][2] = *(const uint32_t*)(ap + 8);
                a[mi][3] = *(const uint32_t*)(ap + 8 * LDV + 8);
            }
#pragma unroll
            for (int ni = 0; ni < 2; ni++) {
                const __half* bp = Vt + (wn * 16 + ni * 8 + gid) * LDV + kk;
                bf[ni][0] = *(const uint32_t*)(bp);
                bf[ni][1] = *(const uint32_t*)(bp + 8);
            }
#pragma unroll
            for (int mi = 0; mi < 2; mi++)
#pragma unroll
                for (int ni = 0; ni < 2; ni++)
                    mma_f16f32(o[mi][ni][0], o[mi][ni][1], o[mi][ni][2], o[mi][ni][3],
                               a[mi][0], a[mi][1], a[mi][2], a[mi][3], bf[ni][0], bf[ni][1]);
        }
#pragma unroll
        for (int mi = 0; mi < 2; mi++) {
#pragma unroll
            for (int half_ = 0; half_ < 2; half_++) {
                int q = q0 + wm * 32 + mi * 16 + gid + half_ * 8;
                if (q >= SEQ) continue;
#pragma unroll
                for (int ni = 0; ni < 2; ni++) {
                    int d = wn * 16 + ni * 8 + 2 * tig;
                    union { __half h[2]; uint32_t u; } P2;
                    P2.h[0] = __float2half_rn(o[mi][ni][half_ * 2 + 0]);
                    P2.h[1] = __float2half_rn(o[mi][ni][half_ * 2 + 1]);
                    *(uint32_t*)(yH + (size_t)(b * SEQ + q) * DMODEL + h * DHEAD + d) = P2.u;
                }
            }
        }
        __syncthreads();
    }
}

// ---- weight convert+transpose: 64x64 tiles, vectorized ----
__global__ __launch_bounds__(256) void wconv_kernel(const float* __restrict__ W,
                                                    __half* __restrict__ out,
                                                    int K, int N) {
    __shared__ float t[64][65];
    W   += (size_t)blockIdx.z * K * N;
    out += (size_t)blockIdx.z * N * K;
    int k0 = blockIdx.y * 64, n0 = blockIdx.x * 64;
    int tid = threadIdx.x;
#pragma unroll
    for (int i = 0; i < 4; i++) {
        int idx = tid + i * 256;
        int r = idx >> 4, c4 = (idx & 15) * 4;
        float4 v = *(const float4*)(W + (size_t)(k0 + r) * N + n0 + c4);
        t[r][c4 + 0] = v.x; t[r][c4 + 1] = v.y; t[r][c4 + 2] = v.z; t[r][c4 + 3] = v.w;
    }
    __syncthreads();
#pragma unroll
    for (int i = 0; i < 4; i++) {
        int idx = tid + i * 256;
        int n = idx >> 4, kq = (idx & 15) * 4;
        __half2 h01 = __floats2half2_rn(t[kq + 0][n], t[kq + 1][n]);
        __half2 h23 = __floats2half2_rn(t[kq + 2][n], t[kq + 3][n]);
        uint2 u;
        u.x = *(uint32_t*)&h01;
        u.y = *(uint32_t*)&h23;
        *(uint2*)(out + (size_t)(n0 + n) * K + k0 + kq) = u;
    }
}

// ---- patch extraction ----
__global__ __launch_bounds__(256) void patch_kernel(const float* __restrict__ img,
                                                    __half* __restrict__ out) {
    int idx = blockIdx.x * 256 + threadIdx.x;
    if (idx >= M_PAT * DMODEL) return;
    int i = idx % DMODEL, row = idx / DMODEL;
    int p = row % NTOK, b = row / NTOK;
    int c = i >> 8, rem = i & 255, iy = rem >> 4, ix = rem & 15;
    int py = p / 14, px = p % 14;
    float v = img[(((size_t)(b*3 + c) * 224) + py*16 + iy) * 224 + px*16 + ix];
    out[idx] = __float2half_rn(v);
}

// ---- embed ----
__global__ __launch_bounds__(256) void embed_kernel(const float* __restrict__ tok,
                                                    const float* __restrict__ v_class,
                                                    float* __restrict__ x) {
    int idx = blockIdx.x * 256 + threadIdx.x;
    if (idx >= M_ALL * DMODEL) return;
    int d = idx % DMODEL, r = idx / DMODEL;
    int s = r % SEQ, b = r / SEQ;
    float t = (s == 0) ? v_class[d] : tok[(size_t)(b * NTOK + s - 1) * DMODEL + d];
    float ang = (float)s * __expf((float)d * (-9.210340371976184f / (float)DMODEL));
    x[idx] = t + (((d & 1) == 0) ? sinf(ang) : cosf(ang));
}

// ---- LayerNorm: warp per row ----
__global__ __launch_bounds__(256) void ln_kernel(const float* __restrict__ x,
                                                 const float* __restrict__ gamma,
                                                 const float* __restrict__ beta,
                                                 __half* __restrict__ outH) {
    int warp = threadIdx.x >> 5, lane = threadIdx.x & 31;
    int row = blockIdx.x * 8 + warp;
    const float4* xr = (const float4*)(x + (size_t)row * DMODEL);
    float4 v[6];
    float sum = 0.0f;
#pragma unroll
    for (int j = 0; j < 6; j++) {
        v[j] = xr[lane + 32 * j];
        sum += v[j].x + v[j].y + v[j].z + v[j].w;
    }
#pragma unroll
    for (int o = 16; o > 0; o >>= 1) sum += __shfl_xor_sync(0xffffffffu, sum, o);
    float mean = sum * (1.0f / DMODEL);
    float var = 0.0f;
#pragma unroll
    for (int j = 0; j < 6; j++) {
        float a = v[j].x - mean, b = v[j].y - mean, c = v[j].z - mean, d = v[j].w - mean;
        var += a*a + b*b + c*c + d*d;
    }
#pragma unroll
    for (int o = 16; o > 0; o >>= 1) var += __shfl_xor_sync(0xffffffffu, var, o);
    float rstd = rsqrtf(var * (1.0f / DMODEL) + 1e-5f);

    const float4* gr = (const float4*)gamma;
    const float4* br = (const float4*)beta;
    uint2* orow = (uint2*)(outH + (size_t)row * DMODEL);
#pragma unroll
    for (int j = 0; j < 6; j++) {
        float4 g = gr[lane + 32 * j], bb = br[lane + 32 * j];
        float o0 = (v[j].x - mean) * rstd * g.x + bb.x;
        float o1 = (v[j].y - mean) * rstd * g.y + bb.y;
        float o2 = (v[j].z - mean) * rstd * g.z + bb.z;
        float o3 = (v[j].w - mean) * rstd * g.w + bb.w;
        __half2 h01 = __floats2half2_rn(o0, o1);
        __half2 h23 = __floats2half2_rn(o2, o3);
        uint2 u;
        u.x = *(uint32_t*)&h01;
        u.y = *(uint32_t*)&h23;
        orow[lane + 32 * j] = u;
    }
}

// ---- KAN head ----
__global__ __launch_bounds__(256) void head_kernel(const float* __restrict__ x,
                                                   const float* __restrict__ amp,
                                                   float* __restrict__ logits) {
    __shared__ float sines[4 * DMODEL];
    int b = blockIdx.x, tid = threadIdx.x;
    const float* xr = x + (size_t)b * SEQ * DMODEL;
    const float PI = 3.14159265358979323846f;
    for (int i = tid; i < DMODEL; i += 256) {
        float xv = xr[i], ph = (float)i * (PI / (float)DMODEL);
#pragma unroll
        for (int g = 0; g < 4; g++) sines[g*DMODEL + i] = sinf(xv * (float)(g+1) + ph);
    }
    __syncthreads();
    int warp = tid >> 5, lane = tid & 31;
    int o = blockIdx.y * 8 + warp;
    if (o < NOUT) {
        const float* ar = amp + (size_t)o * 4 * DMODEL;
        float acc = 0.0f;
        for (int i = lane; i < 4*DMODEL; i += 32) acc = fmaf(sines[i], ar[i], acc);
#pragma unroll
        for (int of = 16; of > 0; of >>= 1) acc += __shfl_xor_sync(0xffffffffu, acc, of);
        if (lane == 0) logits[(size_t)b*NOUT + o] = acc * (1.0f / 55.42562584220407f);
    }
}

// ---- softmax ----
__global__ __launch_bounds__(256) void softmax_kernel(const float* __restrict__ logits,
                                                      float* __restrict__ out) {
    int b = blockIdx.x, tid = threadIdx.x;
    const float* lr = logits + (size_t)b * NOUT;
    __shared__ float red[256];
    float m = -1e30f;
    for (int i = tid; i < NOUT; i += 256) m = fmaxf(m, lr[i]);
    red[tid] = m; __syncthreads();
    for (int o = 128; o > 0; o >>= 1) { if (tid < o) red[tid] = fmaxf(red[tid], red[tid+o]); __syncthreads(); }
    m = red[0]; __syncthreads();
    float s = 0.0f;
    for (int i = tid; i < NOUT; i += 256) s += expf(lr[i] - m);
    red[tid] = s; __syncthreads();
    for (int o = 128; o > 0; o >>= 1) { if (tid < o) red[tid] += red[tid+o]; __syncthreads(); }
    float inv = 1.0f / red[0];
    for (int i = tid; i < NOUT; i += 256) out[(size_t)b*NOUT + i] = expf(lr[i] - m) * inv;
}

// ---- launch ----
extern "C" void kernel_launch(void* const* d_in, const int* in_sizes, int n_in,
                              void* d_out, int out_size) {
    (void)in_sizes; (void)n_in; (void)out_size;
    const float* images    = (const float*)d_in[0];
    const float* v_class   = (const float*)d_in[1];
    const float* W_map     = (const float*)d_in[2];
    const float* b_map     = (const float*)d_in[3];
    const float* ln1_scale = (const float*)d_in[4];
    const float* ln1_bias  = (const float*)d_in[5];
    const float* Wqkv      = (const float*)d_in[6];
    const float* bqkv      = (const float*)d_in[7];
    const float* Wo        = (const float*)d_in[8];
    const float* bo        = (const float*)d_in[9];
    const float* ln2_scale = (const float*)d_in[10];
    const float* ln2_bias  = (const float*)d_in[11];
    const float* Wmlp1     = (const float*)d_in[12];
    const float* bmlp1     = (const float*)d_in[13];
    const float* Wmlp2     = (const float*)d_in[14];
    const float* bmlp2     = (const float*)d_in[15];
    const float* kan_amp   = (const float*)d_in[16];
    float* out = (float*)d_out;

    void *p0,*p1,*p2,*p3,*p4,*p5,*p6,*p7,*p8,*p9,*p10,*p11,*p12;
    cudaGetSymbolAddress(&p0, g_patch_h); cudaGetSymbolAddress(&p1, g_tok);
    cudaGetSymbolAddress(&p2, g_x);       cudaGetSymbolAddress(&p3, g_h_h);
    cudaGetSymbolAddress(&p4, g_qkv_h);   cudaGetSymbolAddress(&p5, g_y_h);
    cudaGetSymbolAddress(&p6, g_ff_h);    cudaGetSymbolAddress(&p7, g_logits);
    cudaGetSymbolAddress(&p8, g_wmap_t);  cudaGetSymbolAddress(&p9, g_wqkv_t);
    cudaGetSymbolAddress(&p10, g_wo_t);   cudaGetSymbolAddress(&p11, g_wm1_t);
    cudaGetSymbolAddress(&p12, g_wm2_t);
    __half* patch_h = (__half*)p0;
    float* tok = (float*)p1;
    float* x   = (float*)p2;
    __half* h_h = (__half*)p3;
    __half* qkv_h = (__half*)p4;
    __half* y_h = (__half*)p5;
    __half* ff_h = (__half*)p6;
    float* logits = (float*)p7;
    __half* wmap_t = (__half*)p8;
    __half* wqkv_t = (__half*)p9;
    __half* wo_t   = (__half*)p10;
    __half* wm1_t  = (__half*)p11;
    __half* wm2_t  = (__half*)p12;

    cudaFuncSetAttribute(attn_kernel, cudaFuncAttributeMaxDynamicSharedMemorySize, (int)ATTN_SMEM);
    cudaFuncSetAttribute(mma_gemm_kernel, cudaFuncAttributeMaxDynamicSharedMemorySize, GEMM_SMEM);

    wconv_kernel<<<dim3(DMODEL/64, DMODEL/64, 1), 256>>>(W_map, wmap_t, DMODEL, DMODEL);
    wconv_kernel<<<dim3(3*DMODEL/64, DMODEL/64, NBLK), 256>>>(Wqkv, wqkv_t, DMODEL, 3*DMODEL);
    wconv_kernel<<<dim3(DMODEL/64, DMODEL/64, NBLK), 256>>>(Wo, wo_t, DMODEL, DMODEL);
    wconv_kernel<<<dim3(FFDIM/64, DMODEL/64, NBLK), 256>>>(Wmlp1, wm1_t, DMODEL, FFDIM);
    wconv_kernel<<<dim3(DMODEL/64, FFDIM/64, NBLK), 256>>>(Wmlp2, wm2_t, FFDIM, DMODEL);

    patch_kernel<<<(M_PAT*DMODEL + 255)/256, 256>>>(images, patch_h);
    mma_gemm_kernel<<<dim3(DMODEL/128, M_PAT/128), 256, GEMM_SMEM>>>(
        patch_h, wmap_t, b_map, nullptr, tok, nullptr, M_PAT, DMODEL, DMODEL, 0);
    embed_kernel<<<(M_ALL*DMODEL + 255)/256, 256>>>(tok, v_class, x);

    for (int blk = 0; blk < NBLK; blk++) {
        ln_kernel<<<M_ALL/8, 256>>>(x, ln1_scale + (size_t)blk*DMODEL, ln1_bias + (size_t)blk*DMODEL, h_h);
        mma_gemm_kernel<<<dim3(3*DMODEL/128, MTILES), 256, GEMM_SMEM>>>(
            h_h, wqkv_t + (size_t)blk*3*DMODEL*DMODEL, bqkv + (size_t)blk*3*DMODEL,
            nullptr, nullptr, qkv_h, M_ALL, 3*DMODEL, DMODEL, 0);
        attn_kernel<<<dim3(NHEAD, BATCH), 256, ATTN_SMEM>>>(qkv_h, y_h);
        mma_gemm_kernel<<<dim3(DMODEL/128, MTILES), 256, GEMM_SMEM>>>(
            y_h, wo_t + (size_t)blk*DMODEL*DMODEL, bo + (size_t)blk*DMODEL,
            x, x, nullptr, M_ALL, DMODEL, DMODEL, 0);
        ln_kernel<<<M_ALL/8, 256>>>(x, ln2_scale + (size_t)blk*DMODEL, ln2_bias + (size_t)blk*DMODEL, h_h);
        mma_gemm_kernel<<<dim3(FFDIM/128, MTILES), 256, GEMM_SMEM>>>(
            h_h, wm1_t + (size_t)blk*FFDIM*DMODEL, bmlp1 + (size_t)blk*FFDIM,
            nullptr, nullptr, ff_h, M_ALL, FFDIM, DMODEL, 1);
        mma_gemm_kernel<<<dim3(DMODEL/128, MTILES), 256, GEMM_SMEM>>>(
            ff_h, wm2_t + (size_t)blk*DMODEL*FFDIM, bmlp2 + (size_t)blk*DMODEL,
            x, x, nullptr, M_ALL, DMODEL, FFDIM, 0);
    }

    head_kernel<<<dim3(BATCH, 125), 256>>>(x, kan_amp, logits);
    softmax_kernel<<<BATCH, 256>>>(logits, out);
}

// round 14
// speedup vs baseline: 1.0366x; 1.0366x over previous
#include <cuda_runtime.h>
#include <cuda_fp16.h>
#include <stdint.h>
#include <math.h>

#define BATCH 64
#define SEQ   197
#define DMODEL 768
#define NBLK  12
#define NHEAD 12
#define DHEAD 64
#define FFDIM 3072
#define NOUT  1000
#define NTOK  196
#define M_ALL (BATCH*SEQ)   // 12608
#define M_PAT (BATCH*NTOK)  // 12544
#define MPAD  12800
#define MTILES 99           // ceil(12608/128)

// ---- scratch ----
__device__ __align__(16) __half g_patch_h[(size_t)M_PAT * DMODEL];
__device__ float  g_tok   [(size_t)M_PAT * DMODEL];
__device__ float  g_x     [(size_t)M_ALL * DMODEL];
__device__ __align__(16) __half g_h_h [(size_t)MPAD * DMODEL];
__device__ __align__(16) __half g_qkv_h[(size_t)M_ALL * 3 * DMODEL];
__device__ __align__(16) __half g_y_h [(size_t)MPAD * DMODEL];
__device__ __align__(16) __half g_ff_h[(size_t)MPAD * FFDIM];
__device__ float  g_logits[BATCH * NOUT];
__device__ __align__(16) __half g_wmap_t[(size_t)DMODEL * DMODEL];
__device__ __align__(16) __half g_wqkv_t[(size_t)NBLK * 3 * DMODEL * DMODEL];
__device__ __align__(16) __half g_wo_t  [(size_t)NBLK * DMODEL * DMODEL];
__device__ __align__(16) __half g_wm1_t [(size_t)NBLK * FFDIM * DMODEL];
__device__ __align__(16) __half g_wm2_t [(size_t)NBLK * DMODEL * FFDIM];

__device__ __forceinline__ void cpasync16(uint32_t s, const void* g) {
    asm volatile("cp.async.cg.shared.global [%0], [%1], 16;" :: "r"(s), "l"(g));
}
__device__ __forceinline__ uint32_t smem_u32(const void* p) {
    uint32_t a;
    asm("{ .reg .u64 t; cvta.to.shared.u64 t, %1; cvt.u32.u64 %0, t; }" : "=r"(a) : "l"(p));
    return a;
}
#define CP_COMMIT() asm volatile("cp.async.commit_group;" ::: "memory")
#define CP_WAIT2()  asm volatile("cp.async.wait_group 2;" ::: "memory")
#define CP_WAIT1()  asm volatile("cp.async.wait_group 1;" ::: "memory")
#define CP_WAIT0()  asm volatile("cp.async.wait_group 0;" ::: "memory")

#define LDSM_X4(r0,r1,r2,r3,addr) \
    asm volatile("ldmatrix.sync.aligned.m8n8.x4.shared.b16 {%0,%1,%2,%3}, [%4];" \
                 : "=r"(r0), "=r"(r1), "=r"(r2), "=r"(r3) : "r"(addr))
#define LDSM_X2(r0,r1,addr) \
    asm volatile("ldmatrix.sync.aligned.m8n8.x2.shared.b16 {%0,%1}, [%2];" \
                 : "=r"(r0), "=r"(r1) : "r"(addr))
#define LDSM_X2T(r0,r1,addr) \
    asm volatile("ldmatrix.sync.aligned.m8n8.x2.trans.shared.b16 {%0,%1}, [%2];" \
                 : "=r"(r0), "=r"(r1) : "r"(addr))

__device__ __forceinline__ void mma_f16f32(float& c0, float& c1, float& c2, float& c3,
                                           uint32_t a0, uint32_t a1, uint32_t a2, uint32_t a3,
                                           uint32_t b0, uint32_t b1) {
    asm volatile("mma.sync.aligned.m16n8k16.row.col.f32.f16.f16.f32 "
                 "{%0,%1,%2,%3}, {%4,%5,%6,%7}, {%8,%9}, {%0,%1,%2,%3};"
                 : "+f"(c0), "+f"(c1), "+f"(c2), "+f"(c3)
                 : "r"(a0), "r"(a1), "r"(a2), "r"(a3), "r"(b0), "r"(b1));
}

// ---- HMMA GEMM, f32 acc, ldmatrix fragments (A x4, B x2), 3-stage cp.async ----
#define LDK 72
#define STAGE_E (128 * LDK)
#define GEMM_SMEM (6 * STAGE_E * 2)   // 110592 B

__global__ __launch_bounds__(256, 2) void mma_gemm_kernel(
    const __half* __restrict__ A, const __half* __restrict__ Bw,
    const float* __restrict__ bias, const float* __restrict__ res,
    float* __restrict__ outF, __half* __restrict__ outS,
    int Mreal, int N, int K, int act)
{
    extern __shared__ __half smem[];
    int tid = threadIdx.x;
    int wid = tid >> 5, lane = tid & 31;
    int warpM = wid & 1, warpN = wid >> 1;
    int gid = lane >> 2, tig = lane & 3;
    int mT = blockIdx.y * 128, nT = blockIdx.x * 128;
    const int C = K / 64;

    const __half* Ab = A + (size_t)mT * K;
    const __half* Bb = Bw + (size_t)nT * K;
    uint32_t sbase = smem_u32(smem);

    int ldrow[4], ldseg[4];
#pragma unroll
    for (int i = 0; i < 4; i++) {
        int c = tid + i * 256;
        ldrow[i] = c >> 3;
        ldseg[i] = c & 7;
    }

    auto load_chunk = [&](int c) {
        int s = c % 3;
        int kOff = c * 64;
        uint32_t sA = sbase + s * (2 * STAGE_E * 2);
        uint32_t sB = sA + STAGE_E * 2;
#pragma unroll
        for (int i = 0; i < 4; i++) {
            int r = ldrow[i], sg = ldseg[i];
            cpasync16(sA + (r * LDK + sg * 8) * 2, Ab + (size_t)r * K + kOff + sg * 8);
            cpasync16(sB + (r * LDK + sg * 8) * 2, Bb + (size_t)r * K + kOff + sg * 8);
        }
        CP_COMMIT();
    };

    float acc[4][4][4];
#pragma unroll
    for (int i = 0; i < 4; i++)
#pragma unroll
        for (int j = 0; j < 4; j++)
#pragma unroll
            for (int k = 0; k < 4; k++) acc[i][j][k] = 0.0f;

    load_chunk(0);
    if (C > 1) load_chunk(1);
    if (C > 2) load_chunk(2);

    int lr = lane & 7;
    uint32_t aRow = (uint32_t)(warpM * 64 + lr + ((lane >> 3) & 1) * 8);
    uint32_t aCol = (uint32_t)(((lane >> 4) & 1) * 8);
    uint32_t bRow = (uint32_t)(warpN * 32 + lr);
    uint32_t bCol = (uint32_t)(((lane >> 3) & 1) * 8);

    for (int c = 0; c < C; c++) {
        int rem = C - 1 - c;
        if (rem >= 2) CP_WAIT2(); else if (rem == 1) CP_WAIT1(); else CP_WAIT0();
        __syncthreads();
        uint32_t sAaddr = sbase + (c % 3) * (2 * STAGE_E * 2);
        uint32_t sBaddr = sAaddr + STAGE_E * 2;
#pragma unroll
        for (int ks = 0; ks < 4; ks++) {
            uint32_t kk0 = ks * 16;
            uint32_t a[4][4], b[4][2];
#pragma unroll
            for (int mt = 0; mt < 4; mt++)
                LDSM_X4(a[mt][0], a[mt][1], a[mt][2], a[mt][3],
                        sAaddr + ((aRow + mt * 16) * LDK + kk0 + aCol) * 2);
#pragma unroll
            for (int nt = 0; nt < 4; nt++)
                LDSM_X2(b[nt][0], b[nt][1],
                        sBaddr + ((bRow + nt * 8) * LDK + kk0 + bCol) * 2);
#pragma unroll
            for (int mt = 0; mt < 4; mt++)
#pragma unroll
                for (int nt = 0; nt < 4; nt++)
                    mma_f16f32(acc[mt][nt][0], acc[mt][nt][1], acc[mt][nt][2], acc[mt][nt][3],
                               a[mt][0], a[mt][1], a[mt][2], a[mt][3], b[nt][0], b[nt][1]);
        }
        __syncthreads();
        if (c + 3 < C) load_chunk(c + 3);
    }

#pragma unroll
    for (int mt = 0; mt < 4; mt++) {
#pragma unroll
        for (int half_ = 0; half_ < 2; half_++) {
            int row = mT + warpM * 64 + mt * 16 + gid + half_ * 8;
            if (row >= Mreal) continue;
#pragma unroll
            for (int nt = 0; nt < 4; nt++) {
                int col = nT + warpN * 32 + nt * 8 + tig * 2;
                float v0 = acc[mt][nt][half_ * 2 + 0];
                float v1 = acc[mt][nt][half_ * 2 + 1];
                float2 bb = *(const float2*)(bias + col);
                v0 += bb.x; v1 += bb.y;
                if (act == 1) {
                    float u;
                    u = v0; v0 = 0.5f*u*(1.0f + tanhf(0.7978845608028654f*(u + 0.044715f*u*u*u)));
                    u = v1; v1 = 0.5f*u*(1.0f + tanhf(0.7978845608028654f*(u + 0.044715f*u*u*u)));
                }
                if (res) {
                    float2 rr = *(const float2*)(res + (size_t)row * N + col);
                    v0 += rr.x; v1 += rr.y;
                }
                if (outF) *(float2*)(outF + (size_t)row * N + col) = make_float2(v0, v1);
                if (outS) {
                    union { __half h[2]; uint32_t u; } P;
                    P.h[0] = __float2half_rn(v0);
                    P.h[1] = __float2half_rn(v1);
                    *(uint32_t*)(outS + (size_t)row * N + col) = P.u;
                }
            }
        }
    }
}

// ---- tensor-core attention: register softmax, 2 CTA/SM, V via ldmatrix.trans ----
#define SP 224
#define LDQK 72
#define LDV 232
#define ATTN_SMEM ((64*LDQK + SP*LDQK + SP*LDQK) * 2 + 64*LDV*2 + 2 * 64 * 4 * 4)

__global__ __launch_bounds__(256, 2) void attn_kernel(const __half* __restrict__ qkv,
                                                      __half* __restrict__ yH) {
    extern __shared__ char smc[];
    __half* Qs = (__half*)smc;              // 64 x 72
    __half* Ks = Qs + 64 * LDQK;            // 224 x 72
    __half* Vs = Ks + SP * LDQK;            // 224 x 72 (row-major, like K)
    __half* Pm = Vs + SP * LDQK;            // 64 x 232
    float*  redA = (float*)(Pm + 64 * LDV); // 64 x 4
    float*  redB = redA + 64 * 4;           // 64 x 4

    int h = blockIdx.x, b = blockIdx.y;
    int tid = threadIdx.x, wid = tid >> 5, lane = tid & 31;
    int gid = lane >> 2, tig = lane & 3;
    int wm = wid >> 2, wn = wid & 3;

    const __half* base = qkv + (size_t)(b * SEQ) * (3 * DMODEL) + h * DHEAD;
    uint32_t vbase = smem_u32(Vs);

    // stage K and V row-major (vectorized), zero-padded to 224 rows
    for (int idx = tid; idx < SP * 32; idx += 256) {
        int t = idx >> 5, p = idx & 31;
        uint32_t kv = 0, vv = 0;
        if (t < SEQ) {
            const __half* rp = base + (size_t)t * (3 * DMODEL);
            kv = *(const uint32_t*)(rp + DMODEL + 2 * p);
            vv = *(const uint32_t*)(rp + 2 * DMODEL + 2 * p);
        }
        *(uint32_t*)(Ks + t * LDQK + 2 * p) = kv;
        *(uint32_t*)(Vs + t * LDQK + 2 * p) = vv;
    }
    __syncthreads();

    for (int q0 = 0; q0 < SP; q0 += 64) {
        // stage Q chunk (x 0.125)
        for (int idx = tid; idx < 64 * 32; idx += 256) {
            int rl = idx >> 5, p = idx & 31;
            int t = q0 + rl;
            uint32_t qv = 0;
            if (t < SEQ) {
                __half2 q2 = *(const __half2*)(base + (size_t)t * (3 * DMODEL) + 2 * p);
                float2 qf = __half22float2(q2);
                __half2 qs = __floats2half2_rn(qf.x * 0.125f, qf.y * 0.125f);
                qv = *(uint32_t*)&qs;
            }
            *(uint32_t*)(Qs + rl * LDQK + 2 * p) = qv;
        }
        __syncthreads();

        // S = Qchunk @ K^T : warp tile 32x56
        float c[2][7][4];
#pragma unroll
        for (int mi = 0; mi < 2; mi++)
#pragma unroll
            for (int ni = 0; ni < 7; ni++)
#pragma unroll
                for (int k = 0; k < 4; k++) c[mi][ni][k] = 0.0f;
#pragma unroll
        for (int ks = 0; ks < 4; ks++) {
            int kk = ks * 16 + tig * 2;
            uint32_t a[2][4], bf[7][2];
#pragma unroll
            for (int mi = 0; mi < 2; mi++) {
                const __half* ap = Qs + (wm * 32 + mi * 16 + gid) * LDQK + kk;
                a[mi][0] = *(const uint32_t*)(ap);
                a[mi][1] = *(const uint32_t*)(ap + 8 * LDQK);
                a[mi][2] = *(const uint32_t*)(ap + 8);
                a[mi][3] = *(const uint32_t*)(ap + 8 * LDQK + 8);
            }
#pragma unroll
            for (int ni = 0; ni < 7; ni++) {
                const __half* bp = Ks + (wn * 56 + ni * 8 + gid) * LDQK + kk;
                bf[ni][0] = *(const uint32_t*)(bp);
                bf[ni][1] = *(const uint32_t*)(bp + 8);
            }
#pragma unroll
            for (int mi = 0; mi < 2; mi++)
#pragma unroll
                for (int ni = 0; ni < 7; ni++)
                    mma_f16f32(c[mi][ni][0], c[mi][ni][1], c[mi][ni][2], c[mi][ni][3],
                               a[mi][0], a[mi][1], a[mi][2], a[mi][3], bf[ni][0], bf[ni][1]);
        }

        // mask padded key columns
#pragma unroll
        for (int ni = 0; ni < 7; ni++) {
            int col = wn * 56 + ni * 8 + 2 * tig;
            if (col >= SEQ) { c[0][ni][0] = c[0][ni][2] = c[1][ni][0] = c[1][ni][2] = -1e30f; }
            if (col + 1 >= SEQ) { c[0][ni][1] = c[0][ni][3] = c[1][ni][1] = c[1][ni][3] = -1e30f; }
        }

        // row max partials
#pragma unroll
        for (int mi = 0; mi < 2; mi++) {
            float m0 = -1e30f, m1 = -1e30f;
#pragma unroll
            for (int ni = 0; ni < 7; ni++) {
                m0 = fmaxf(m0, fmaxf(c[mi][ni][0], c[mi][ni][1]));
                m1 = fmaxf(m1, fmaxf(c[mi][ni][2], c[mi][ni][3]));
            }
#pragma unroll
            for (int o = 1; o <= 2; o <<= 1) {
                m0 = fmaxf(m0, __shfl_xor_sync(0xffffffffu, m0, o));
                m1 = fmaxf(m1, __shfl_xor_sync(0xffffffffu, m1, o));
            }
            if (tig == 0) {
                int rr = wm * 32 + mi * 16 + gid;
                redA[rr * 4 + wn] = m0;
                redA[(rr + 8) * 4 + wn] = m1;
            }
        }
        __syncthreads();

        // exp + partial sums
#pragma unroll
        for (int mi = 0; mi < 2; mi++) {
            int rr = wm * 32 + mi * 16 + gid;
            float4 ra = *(const float4*)(redA + rr * 4);
            float4 rb = *(const float4*)(redA + (rr + 8) * 4);
            float m0 = fmaxf(fmaxf(ra.x, ra.y), fmaxf(ra.z, ra.w));
            float m1 = fmaxf(fmaxf(rb.x, rb.y), fmaxf(rb.z, rb.w));
            float s0 = 0.0f, s1 = 0.0f;
#pragma unroll
            for (int ni = 0; ni < 7; ni++) {
                float e0 = __expf(c[mi][ni][0] - m0);
                float e1 = __expf(c[mi][ni][1] - m0);
                float e2 = __expf(c[mi][ni][2] - m1);
                float e3 = __expf(c[mi][ni][3] - m1);
                c[mi][ni][0] = e0; c[mi][ni][1] = e1; c[mi][ni][2] = e2; c[mi][ni][3] = e3;
                s0 += e0 + e1; s1 += e2 + e3;
            }
#pragma unroll
            for (int o = 1; o <= 2; o <<= 1) {
                s0 += __shfl_xor_sync(0xffffffffu, s0, o);
                s1 += __shfl_xor_sync(0xffffffffu, s1, o);
            }
            if (tig == 0) {
                redB[rr * 4 + wn] = s0;
                redB[(rr + 8) * 4 + wn] = s1;
            }
        }
        __syncthreads();

        // normalize -> Pm fp16
#pragma unroll
        for (int mi = 0; mi < 2; mi++) {
            int rr = wm * 32 + mi * 16 + gid;
            float4 ra = *(const float4*)(redB + rr * 4);
            float4 rb = *(const float4*)(redB + (rr + 8) * 4);
            float i0 = 1.0f / (ra.x + ra.y + ra.z + ra.w);
            float i1 = 1.0f / (rb.x + rb.y + rb.z + rb.w);
#pragma unroll
            for (int ni = 0; ni < 7; ni++) {
                int col = wn * 56 + ni * 8 + 2 * tig;
                __half2 p0 = __floats2half2_rn(c[mi][ni][0] * i0, c[mi][ni][1] * i0);
                __half2 p1 = __floats2half2_rn(c[mi][ni][2] * i1, c[mi][ni][3] * i1);
                *(__half2*)(Pm + rr * LDV + col) = p0;
                *(__half2*)(Pm + (rr + 8) * LDV + col) = p1;
            }
        }
        __syncthreads();

        // O = P @ V^T : warp tile 32x16, k=224, V B-fragments via ldmatrix.trans
        float o[2][2][4];
#pragma unroll
        for (int mi = 0; mi < 2; mi++)
#pragma unroll
            for (int ni = 0; ni < 2; ni++)
#pragma unroll
                for (int k = 0; k < 4; k++) o[mi][ni][k] = 0.0f;

        int trow = (lane & 7) + ((lane >> 3) & 1) * 8;  // k-row within 16 for lanes 0..15
#pragma unroll
        for (int ks = 0; ks < 14; ks++) {
            int kk = ks * 16 + tig * 2;
            uint32_t a[2][4], bf[2][2];
#pragma unroll
            for (int mi = 0; mi < 2; mi++) {
                const __half* ap = Pm + (wm * 32 + mi * 16 + gid) * LDV + kk;
                a[mi][0] = *(const uint32_t*)(ap);
                a[mi][1] = *(const uint32_t*)(ap + 8 * LDV);
                a[mi][2] = *(const uint32_t*)(ap + 8);
                a[mi][3] = *(const uint32_t*)(ap + 8 * LDV + 8);
            }
#pragma unroll
            for (int ni = 0; ni < 2; ni++) {
                int d0 = wn * 16 + ni * 8;
                uint32_t addr = vbase + (((uint32_t)(ks * 16 + trow)) * LDQK + d0) * 2;
                LDSM_X2T(bf[ni][0], bf[ni][1], addr);
            }
#pragma unroll
            for (int mi = 0; mi < 2; mi++)
#pragma unroll
                for (int ni = 0; ni < 2; ni++)
                    mma_f16f32(o[mi][ni][0], o[mi][ni][1], o[mi][ni][2], o[mi][ni][3],
                               a[mi][0], a[mi][1], a[mi][2], a[mi][3], bf[ni][0], bf[ni][1]);
        }
#pragma unroll
        for (int mi = 0; mi < 2; mi++) {
#pragma unroll
            for (int half_ = 0; half_ < 2; half_++) {
                int q = q0 + wm * 32 + mi * 16 + gid + half_ * 8;
                if (q >= SEQ) continue;
#pragma unroll
                for (int ni = 0; ni < 2; ni++) {
                    int d = wn * 16 + ni * 8 + 2 * tig;
                    union { __half h[2]; uint32_t u; } P2;
                    P2.h[0] = __float2half_rn(o[mi][ni][half_ * 2 + 0]);
                    P2.h[1] = __float2half_rn(o[mi][ni][half_ * 2 + 1]);
                    *(uint32_t*)(yH + (size_t)(b * SEQ + q) * DMODEL + h * DHEAD + d) = P2.u;
                }
            }
        }
        __syncthreads();
    }
}

// ---- weight convert+transpose: 64x64 tiles, vectorized ----
__global__ __launch_bounds__(256) void wconv_kernel(const float* __restrict__ W,
                                                    __half* __restrict__ out,
                                                    int K, int N) {
    __shared__ float t[64][65];
    W   += (size_t)blockIdx.z * K * N;
    out += (size_t)blockIdx.z * N * K;
    int k0 = blockIdx.y * 64, n0 = blockIdx.x * 64;
    int tid = threadIdx.x;
#pragma unroll
    for (int i = 0; i < 4; i++) {
        int idx = tid + i * 256;
        int r = idx >> 4, c4 = (idx & 15) * 4;
        float4 v = *(const float4*)(W + (size_t)(k0 + r) * N + n0 + c4);
        t[r][c4 + 0] = v.x; t[r][c4 + 1] = v.y; t[r][c4 + 2] = v.z; t[r][c4 + 3] = v.w;
    }
    __syncthreads();
#pragma unroll
    for (int i = 0; i < 4; i++) {
        int idx = tid + i * 256;
        int n = idx >> 4, kq = (idx & 15) * 4;
        __half2 h01 = __floats2half2_rn(t[kq + 0][n], t[kq + 1][n]);
        __half2 h23 = __floats2half2_rn(t[kq + 2][n], t[kq + 3][n]);
        uint2 u;
        u.x = *(uint32_t*)&h01;
        u.y = *(uint32_t*)&h23;
        *(uint2*)(out + (size_t)(n0 + n) * K + k0 + kq) = u;
    }
}

// ---- patch extraction ----
__global__ __launch_bounds__(256) void patch_kernel(const float* __restrict__ img,
                                                    __half* __restrict__ out) {
    int idx = blockIdx.x * 256 + threadIdx.x;
    if (idx >= M_PAT * DMODEL) return;
    int i = idx % DMODEL, row = idx / DMODEL;
    int p = row % NTOK, b = row / NTOK;
    int c = i >> 8, rem = i & 255, iy = rem >> 4, ix = rem & 15;
    int py = p / 14, px = p % 14;
    float v = img[(((size_t)(b*3 + c) * 224) + py*16 + iy) * 224 + px*16 + ix];
    out[idx] = __float2half_rn(v);
}

// ---- embed ----
__global__ __launch_bounds__(256) void embed_kernel(const float* __restrict__ tok,
                                                    const float* __restrict__ v_class,
                                                    float* __restrict__ x) {
    int idx = blockIdx.x * 256 + threadIdx.x;
    if (idx >= M_ALL * DMODEL) return;
    int d = idx % DMODEL, r = idx / DMODEL;
    int s = r % SEQ, b = r / SEQ;
    float t = (s == 0) ? v_class[d] : tok[(size_t)(b * NTOK + s - 1) * DMODEL + d];
    float ang = (float)s * __expf((float)d * (-9.210340371976184f / (float)DMODEL));
    x[idx] = t + (((d & 1) == 0) ? sinf(ang) : cosf(ang));
}

// ---- LayerNorm: warp per row ----
__global__ __launch_bounds__(256) void ln_kernel(const float* __restrict__ x,
                                                 const float* __restrict__ gamma,
                                                 const float* __restrict__ beta,
                                                 __half* __restrict__ outH) {
    int warp = threadIdx.x >> 5, lane = threadIdx.x & 31;
    int row = blockIdx.x * 8 + warp;
    const float4* xr = (const float4*)(x + (size_t)row * DMODEL);
    float4 v[6];
    float sum = 0.0f;
#pragma unroll
    for (int j = 0; j < 6; j++) {
        v[j] = xr[lane + 32 * j];
        sum += v[j].x + v[j].y + v[j].z + v[j].w;
    }
#pragma unroll
    for (int o = 16; o > 0; o >>= 1) sum += __shfl_xor_sync(0xffffffffu, sum, o);
    float mean = sum * (1.0f / DMODEL);
    float var = 0.0f;
#pragma unroll
    for (int j = 0; j < 6; j++) {
        float a = v[j].x - mean, b = v[j].y - mean, c = v[j].z - mean, d = v[j].w - mean;
        var += a*a + b*b + c*c + d*d;
    }
#pragma unroll
    for (int o = 16; o > 0; o >>= 1) var += __shfl_xor_sync(0xffffffffu, var, o);
    float rstd = rsqrtf(var * (1.0f / DMODEL) + 1e-5f);

    const float4* gr = (const float4*)gamma;
    const float4* br = (const float4*)beta;
    uint2* orow = (uint2*)(outH + (size_t)row * DMODEL);
#pragma unroll
    for (int j = 0; j < 6; j++) {
        float4 g = gr[lane + 32 * j], bb = br[lane + 32 * j];
        float o0 = (v[j].x - mean) * rstd * g.x + bb.x;
        float o1 = (v[j].y - mean) * rstd * g.y + bb.y;
        float o2 = (v[j].z - mean) * rstd * g.z + bb.z;
        float o3 = (v[j].w - mean) * rstd * g.w + bb.w;
        __half2 h01 = __floats2half2_rn(o0, o1);
        __half2 h23 = __floats2half2_rn(o2, o3);
        uint2 u;
        u.x = *(uint32_t*)&h01;
        u.y = *(uint32_t*)&h23;
        orow[lane + 32 * j] = u;
    }
}

// ---- KAN head ----
__global__ __launch_bounds__(256) void head_kernel(const float* __restrict__ x,
                                                   const float* __restrict__ amp,
                                                   float* __restrict__ logits) {
    __shared__ float sines[4 * DMODEL];
    int b = blockIdx.x, tid = threadIdx.x;
    const float* xr = x + (size_t)b * SEQ * DMODEL;
    const float PI = 3.14159265358979323846f;
    for (int i = tid; i < DMODEL; i += 256) {
        float xv = xr[i], ph = (float)i * (PI / (float)DMODEL);
#pragma unroll
        for (int g = 0; g < 4; g++) sines[g*DMODEL + i] = sinf(xv * (float)(g+1) + ph);
    }
    __syncthreads();
    int warp = tid >> 5, lane = tid & 31;
    int o = blockIdx.y * 8 + warp;
    if (o < NOUT) {
        const float* ar = amp + (size_t)o * 4 * DMODEL;
        float acc = 0.0f;
        for (int i = lane; i < 4*DMODEL; i += 32) acc = fmaf(sines[i], ar[i], acc);
#pragma unroll
        for (int of = 16; of > 0; of >>= 1) acc += __shfl_xor_sync(0xffffffffu, acc, of);
        if (lane == 0) logits[(size_t)b*NOUT + o] = acc * (1.0f / 55.42562584220407f);
    }
}

// ---- softmax ----
__global__ __launch_bounds__(256) void softmax_kernel(const float* __restrict__ logits,
                                                      float* __restrict__ out) {
    int b = blockIdx.x, tid = threadIdx.x;
    const float* lr = logits + (size_t)b * NOUT;
    __shared__ float red[256];
    float m = -1e30f;
    for (int i = tid; i < NOUT; i += 256) m = fmaxf(m, lr[i]);
    red[tid] = m; __syncthreads();
    for (int o = 128; o > 0; o >>= 1) { if (tid < o) red[tid] = fmaxf(red[tid], red[tid+o]); __syncthreads(); }
    m = red[0]; __syncthreads();
    float s = 0.0f;
    for (int i = tid; i < NOUT; i += 256) s += expf(lr[i] - m);
    red[tid] = s; __syncthreads();
    for (int o = 128; o > 0; o >>= 1) { if (tid < o) red[tid] += red[tid+o]; __syncthreads(); }
    float inv = 1.0f / red[0];
    for (int i = tid; i < NOUT; i += 256) out[(size_t)b*NOUT + i] = expf(lr[i] - m) * inv;
}

// ---- launch ----
extern "C" void kernel_launch(void* const* d_in, const int* in_sizes, int n_in,
                              void* d_out, int out_size) {
    (void)in_sizes; (void)n_in; (void)out_size;
    const float* images    = (const float*)d_in[0];
    const float* v_class   = (const float*)d_in[1];
    const float* W_map     = (const float*)d_in[2];
    const float* b_map     = (const float*)d_in[3];
    const float* ln1_scale = (const float*)d_in[4];
    const float* ln1_bias  = (const float*)d_in[5];
    const float* Wqkv      = (const float*)d_in[6];
    const float* bqkv      = (const float*)d_in[7];
    const float* Wo        = (const float*)d_in[8];
    const float* bo        = (const float*)d_in[9];
    const float* ln2_scale = (const float*)d_in[10];
    const float* ln2_bias  = (const float*)d_in[11];
    const float* Wmlp1     = (const float*)d_in[12];
    const float* bmlp1     = (const float*)d_in[13];
    const float* Wmlp2     = (const float*)d_in[14];
    const float* bmlp2     = (const float*)d_in[15];
    const float* kan_amp   = (const float*)d_in[16];
    float* out = (float*)d_out;

    void *p0,*p1,*p2,*p3,*p4,*p5,*p6,*p7,*p8,*p9,*p10,*p11,*p12;
    cudaGetSymbolAddress(&p0, g_patch_h); cudaGetSymbolAddress(&p1, g_tok);
    cudaGetSymbolAddress(&p2, g_x);       cudaGetSymbolAddress(&p3, g_h_h);
    cudaGetSymbolAddress(&p4, g_qkv_h);   cudaGetSymbolAddress(&p5, g_y_h);
    cudaGetSymbolAddress(&p6, g_ff_h);    cudaGetSymbolAddress(&p7, g_logits);
    cudaGetSymbolAddress(&p8, g_wmap_t);  cudaGetSymbolAddress(&p9, g_wqkv_t);
    cudaGetSymbolAddress(&p10, g_wo_t);   cudaGetSymbolAddress(&p11, g_wm1_t);
    cudaGetSymbolAddress(&p12, g_wm2_t);
    __half* patch_h = (__half*)p0;
    float* tok = (float*)p1;
    float* x   = (float*)p2;
    __half* h_h = (__half*)p3;
    __half* qkv_h = (__half*)p4;
    __half* y_h = (__half*)p5;
    __half* ff_h = (__half*)p6;
    float* logits = (float*)p7;
    __half* wmap_t = (__half*)p8;
    __half* wqkv_t = (__half*)p9;
    __half* wo_t   = (__half*)p10;
    __half* wm1_t  = (__half*)p11;
    __half* wm2_t  = (__half*)p12;

    cudaFuncSetAttribute(attn_kernel, cudaFuncAttributeMaxDynamicSharedMemorySize, (int)ATTN_SMEM);
    cudaFuncSetAttribute(mma_gemm_kernel, cudaFuncAttributeMaxDynamicSharedMemorySize, GEMM_SMEM);

    wconv_kernel<<<dim3(DMODEL/64, DMODEL/64, 1), 256>>>(W_map, wmap_t, DMODEL, DMODEL);
    wconv_kernel<<<dim3(3*DMODEL/64, DMODEL/64, NBLK), 256>>>(Wqkv, wqkv_t, DMODEL, 3*DMODEL);
    wconv_kernel<<<dim3(DMODEL/64, DMODEL/64, NBLK), 256>>>(Wo, wo_t, DMODEL, DMODEL);
    wconv_kernel<<<dim3(FFDIM/64, DMODEL/64, NBLK), 256>>>(Wmlp1, wm1_t, DMODEL, FFDIM);
    wconv_kernel<<<dim3(DMODEL/64, FFDIM/64, NBLK), 256>>>(Wmlp2, wm2_t, FFDIM, DMODEL);

    patch_kernel<<<(M_PAT*DMODEL + 255)/256, 256>>>(images, patch_h);
    mma_gemm_kernel<<<dim3(DMODEL/128, M_PAT/128), 256, GEMM_SMEM>>>(
        patch_h, wmap_t, b_map, nullptr, tok, nullptr, M_PAT, DMODEL, DMODEL, 0);
    embed_kernel<<<(M_ALL*DMODEL + 255)/256, 256>>>(tok, v_class, x);

    for (int blk = 0; blk < NBLK; blk++) {
        ln_kernel<<<M_ALL/8, 256>>>(x, ln1_scale + (size_t)blk*DMODEL, ln1_bias + (size_t)blk*DMODEL, h_h);
        mma_gemm_kernel<<<dim3(3*DMODEL/128, MTILES), 256, GEMM_SMEM>>>(
            h_h, wqkv_t + (size_t)blk*3*DMODEL*DMODEL, bqkv + (size_t)blk*3*DMODEL,
            nullptr, nullptr, qkv_h, M_ALL, 3*DMODEL, DMODEL, 0);
        attn_kernel<<<dim3(NHEAD, BATCH), 256, ATTN_SMEM>>>(qkv_h, y_h);
        mma_gemm_kernel<<<dim3(DMODEL/128, MTILES), 256, GEMM_SMEM>>>(
            y_h, wo_t + (size_t)blk*DMODEL*DMODEL, bo + (size_t)blk*DMODEL,
            x, x, nullptr, M_ALL, DMODEL, DMODEL, 0);
        ln_kernel<<<M_ALL/8, 256>>>(x, ln2_scale + (size_t)blk*DMODEL, ln2_bias + (size_t)blk*DMODEL, h_h);
        mma_gemm_kernel<<<dim3(FFDIM/128, MTILES), 256, GEMM_SMEM>>>(
            h_h, wm1_t + (size_t)blk*FFDIM*DMODEL, bmlp1 + (size_t)blk*FFDIM,
            nullptr, nullptr, ff_h, M_ALL, FFDIM, DMODEL, 1);
        mma_gemm_kernel<<<dim3(DMODEL/128, MTILES), 256, GEMM_SMEM>>>(
            ff_h, wm2_t + (size_t)blk*DMODEL*FFDIM, bmlp2 + (size_t)blk*DMODEL,
            x, x, nullptr, M_ALL, DMODEL, FFDIM, 0);
    }

    head_kernel<<<dim3(BATCH, 125), 256>>>(x, kan_amp, logits);
    softmax_kernel<<<BATCH, 256>>>(logits, out);
}

// round 15
// speedup vs baseline: 1.0413x; 1.0046x over previous
#include <cuda_runtime.h>
#include <cuda_fp16.h>
#include <stdint.h>
#include <math.h>

#define BATCH 64
#define SEQ   197
#define DMODEL 768
#define NBLK  12
#define NHEAD 12
#define DHEAD 64
#define FFDIM 3072
#define NOUT  1000
#define NTOK  196
#define M_ALL (BATCH*SEQ)   // 12608
#define M_PAT (BATCH*NTOK)  // 12544
#define MPAD  12800
#define MTILES 99           // ceil(12608/128)

// ---- scratch ----
__device__ __align__(16) __half g_patch_h[(size_t)M_PAT * DMODEL];
__device__ float  g_tok   [(size_t)M_PAT * DMODEL];
__device__ float  g_x     [(size_t)M_ALL * DMODEL];
__device__ __align__(16) __half g_h_h [(size_t)MPAD * DMODEL];
__device__ __align__(16) __half g_qkv_h[(size_t)M_ALL * 3 * DMODEL];
__device__ __align__(16) __half g_y_h [(size_t)MPAD * DMODEL];
__device__ __align__(16) __half g_ff_h[(size_t)MPAD * FFDIM];
__device__ float  g_logits[BATCH * NOUT];
__device__ __align__(16) __half g_wmap_t[(size_t)DMODEL * DMODEL];
__device__ __align__(16) __half g_wqkv_t[(size_t)NBLK * 3 * DMODEL * DMODEL];
__device__ __align__(16) __half g_wo_t  [(size_t)NBLK * DMODEL * DMODEL];
__device__ __align__(16) __half g_wm1_t [(size_t)NBLK * FFDIM * DMODEL];
__device__ __align__(16) __half g_wm2_t [(size_t)NBLK * DMODEL * FFDIM];

__device__ __forceinline__ void cpasync16(uint32_t s, const void* g) {
    asm volatile("cp.async.cg.shared.global [%0], [%1], 16;" :: "r"(s), "l"(g));
}
__device__ __forceinline__ uint32_t smem_u32(const void* p) {
    uint32_t a;
    asm("{ .reg .u64 t; cvta.to.shared.u64 t, %1; cvt.u32.u64 %0, t; }" : "=r"(a) : "l"(p));
    return a;
}
#define CP_COMMIT() asm volatile("cp.async.commit_group;" ::: "memory")
#define CP_WAIT2()  asm volatile("cp.async.wait_group 2;" ::: "memory")
#define CP_WAIT1()  asm volatile("cp.async.wait_group 1;" ::: "memory")
#define CP_WAIT0()  asm volatile("cp.async.wait_group 0;" ::: "memory")

#define LDSM_X4(r0,r1,r2,r3,addr) \
    asm volatile("ldmatrix.sync.aligned.m8n8.x4.shared.b16 {%0,%1,%2,%3}, [%4];" \
                 : "=r"(r0), "=r"(r1), "=r"(r2), "=r"(r3) : "r"(addr))
#define LDSM_X2(r0,r1,addr) \
    asm volatile("ldmatrix.sync.aligned.m8n8.x2.shared.b16 {%0,%1}, [%2];" \
                 : "=r"(r0), "=r"(r1) : "r"(addr))
#define LDSM_X2T(r0,r1,addr) \
    asm volatile("ldmatrix.sync.aligned.m8n8.x2.trans.shared.b16 {%0,%1}, [%2];" \
                 : "=r"(r0), "=r"(r1) : "r"(addr))

__device__ __forceinline__ void mma_f16f32(float& c0, float& c1, float& c2, float& c3,
                                           uint32_t a0, uint32_t a1, uint32_t a2, uint32_t a3,
                                           uint32_t b0, uint32_t b1) {
    asm volatile("mma.sync.aligned.m16n8k16.row.col.f32.f16.f16.f32 "
                 "{%0,%1,%2,%3}, {%4,%5,%6,%7}, {%8,%9}, {%0,%1,%2,%3};"
                 : "+f"(c0), "+f"(c1), "+f"(c2), "+f"(c3)
                 : "r"(a0), "r"(a1), "r"(a2), "r"(a3), "r"(b0), "r"(b1));
}

// ---- HMMA GEMM, f32 acc, ldmatrix fragments (A x4, B x2), 3-stage cp.async ----
#define LDK 72
#define STAGE_E (128 * LDK)
#define GEMM_SMEM (6 * STAGE_E * 2)   // 110592 B

__global__ __launch_bounds__(256, 2) void mma_gemm_kernel(
    const __half* __restrict__ A, const __half* __restrict__ Bw,
    const float* __restrict__ bias, const float* __restrict__ res,
    float* __restrict__ outF, __half* __restrict__ outS,
    int Mreal, int N, int K, int act)
{
    extern __shared__ __half smem[];
    int tid = threadIdx.x;
    int wid = tid >> 5, lane = tid & 31;
    int warpM = wid & 1, warpN = wid >> 1;
    int gid = lane >> 2, tig = lane & 3;
    int mT = blockIdx.y * 128, nT = blockIdx.x * 128;
    const int C = K / 64;

    const __half* Ab = A + (size_t)mT * K;
    const __half* Bb = Bw + (size_t)nT * K;
    uint32_t sbase = smem_u32(smem);

    int ldrow[4], ldseg[4];
#pragma unroll
    for (int i = 0; i < 4; i++) {
        int c = tid + i * 256;
        ldrow[i] = c >> 3;
        ldseg[i] = c & 7;
    }

    auto load_chunk = [&](int c) {
        int s = c % 3;
        int kOff = c * 64;
        uint32_t sA = sbase + s * (2 * STAGE_E * 2);
        uint32_t sB = sA + STAGE_E * 2;
#pragma unroll
        for (int i = 0; i < 4; i++) {
            int r = ldrow[i], sg = ldseg[i];
            cpasync16(sA + (r * LDK + sg * 8) * 2, Ab + (size_t)r * K + kOff + sg * 8);
            cpasync16(sB + (r * LDK + sg * 8) * 2, Bb + (size_t)r * K + kOff + sg * 8);
        }
        CP_COMMIT();
    };

    float acc[4][4][4];
#pragma unroll
    for (int i = 0; i < 4; i++)
#pragma unroll
        for (int j = 0; j < 4; j++)
#pragma unroll
            for (int k = 0; k < 4; k++) acc[i][j][k] = 0.0f;

    load_chunk(0);
    if (C > 1) load_chunk(1);
    if (C > 2) load_chunk(2);

    int lr = lane & 7;
    uint32_t aRow = (uint32_t)(warpM * 64 + lr + ((lane >> 3) & 1) * 8);
    uint32_t aCol = (uint32_t)(((lane >> 4) & 1) * 8);
    uint32_t bRow = (uint32_t)(warpN * 32 + lr);
    uint32_t bCol = (uint32_t)(((lane >> 3) & 1) * 8);

    for (int c = 0; c < C; c++) {
        int rem = C - 1 - c;
        if (rem >= 2) CP_WAIT2(); else if (rem == 1) CP_WAIT1(); else CP_WAIT0();
        __syncthreads();
        uint32_t sAaddr = sbase + (c % 3) * (2 * STAGE_E * 2);
        uint32_t sBaddr = sAaddr + STAGE_E * 2;
#pragma unroll
        for (int ks = 0; ks < 4; ks++) {
            uint32_t kk0 = ks * 16;
            uint32_t a[4][4], b[4][2];
#pragma unroll
            for (int mt = 0; mt < 4; mt++)
                LDSM_X4(a[mt][0], a[mt][1], a[mt][2], a[mt][3],
                        sAaddr + ((aRow + mt * 16) * LDK + kk0 + aCol) * 2);
#pragma unroll
            for (int nt = 0; nt < 4; nt++)
                LDSM_X2(b[nt][0], b[nt][1],
                        sBaddr + ((bRow + nt * 8) * LDK + kk0 + bCol) * 2);
#pragma unroll
            for (int mt = 0; mt < 4; mt++)
#pragma unroll
                for (int nt = 0; nt < 4; nt++)
                    mma_f16f32(acc[mt][nt][0], acc[mt][nt][1], acc[mt][nt][2], acc[mt][nt][3],
                               a[mt][0], a[mt][1], a[mt][2], a[mt][3], b[nt][0], b[nt][1]);
        }
        __syncthreads();
        if (c + 3 < C) load_chunk(c + 3);
    }

#pragma unroll
    for (int mt = 0; mt < 4; mt++) {
#pragma unroll
        for (int half_ = 0; half_ < 2; half_++) {
            int row = mT + warpM * 64 + mt * 16 + gid + half_ * 8;
            if (row >= Mreal) continue;
#pragma unroll
            for (int nt = 0; nt < 4; nt++) {
                int col = nT + warpN * 32 + nt * 8 + tig * 2;
                float v0 = acc[mt][nt][half_ * 2 + 0];
                float v1 = acc[mt][nt][half_ * 2 + 1];
                float2 bb = *(const float2*)(bias + col);
                v0 += bb.x; v1 += bb.y;
                if (act == 1) {
                    float u;
                    u = v0; v0 = 0.5f*u*(1.0f + tanhf(0.7978845608028654f*(u + 0.044715f*u*u*u)));
                    u = v1; v1 = 0.5f*u*(1.0f + tanhf(0.7978845608028654f*(u + 0.044715f*u*u*u)));
                }
                if (res) {
                    float2 rr = *(const float2*)(res + (size_t)row * N + col);
                    v0 += rr.x; v1 += rr.y;
                }
                if (outF) *(float2*)(outF + (size_t)row * N + col) = make_float2(v0, v1);
                if (outS) {
                    union { __half h[2]; uint32_t u; } P;
                    P.h[0] = __float2half_rn(v0);
                    P.h[1] = __float2half_rn(v1);
                    *(uint32_t*)(outS + (size_t)row * N + col) = P.u;
                }
            }
        }
    }
}

// ---- tensor-core attention: register softmax, 2 CTA/SM, all fragments via ldmatrix ----
#define SP 224
#define LDQK 72
#define LDV 232
#define ATTN_SMEM ((64*LDQK + SP*LDQK + SP*LDQK) * 2 + 64*LDV*2 + 2 * 64 * 4 * 4)

__global__ __launch_bounds__(256, 2) void attn_kernel(const __half* __restrict__ qkv,
                                                      __half* __restrict__ yH) {
    extern __shared__ char smc[];
    __half* Qs = (__half*)smc;              // 64 x 72
    __half* Ks = Qs + 64 * LDQK;            // 224 x 72
    __half* Vs = Ks + SP * LDQK;            // 224 x 72 (row-major)
    __half* Pm = Vs + SP * LDQK;            // 64 x 232
    float*  redA = (float*)(Pm + 64 * LDV); // 64 x 4
    float*  redB = redA + 64 * 4;           // 64 x 4

    int h = blockIdx.x, b = blockIdx.y;
    int tid = threadIdx.x, wid = tid >> 5, lane = tid & 31;
    int gid = lane >> 2, tig = lane & 3;
    int wm = wid >> 2, wn = wid & 3;

    const __half* base = qkv + (size_t)(b * SEQ) * (3 * DMODEL) + h * DHEAD;
    uint32_t qbase = smem_u32(Qs);
    uint32_t kbase = smem_u32(Ks);
    uint32_t vbase = smem_u32(Vs);
    uint32_t pbase = smem_u32(Pm);

    int lr = lane & 7;
    uint32_t aRowOff = (uint32_t)(lr + ((lane >> 3) & 1) * 8);
    uint32_t aColOff = (uint32_t)(((lane >> 4) & 1) * 8);
    uint32_t bColOff = (uint32_t)(((lane >> 3) & 1) * 8);

    // stage K and V row-major (vectorized), zero-padded to 224 rows
    for (int idx = tid; idx < SP * 32; idx += 256) {
        int t = idx >> 5, p = idx & 31;
        uint32_t kv = 0, vv = 0;
        if (t < SEQ) {
            const __half* rp = base + (size_t)t * (3 * DMODEL);
            kv = *(const uint32_t*)(rp + DMODEL + 2 * p);
            vv = *(const uint32_t*)(rp + 2 * DMODEL + 2 * p);
        }
        *(uint32_t*)(Ks + t * LDQK + 2 * p) = kv;
        *(uint32_t*)(Vs + t * LDQK + 2 * p) = vv;
    }
    __syncthreads();

    for (int q0 = 0; q0 < SP; q0 += 64) {
        // stage Q chunk (x 0.125)
        for (int idx = tid; idx < 64 * 32; idx += 256) {
            int rl = idx >> 5, p = idx & 31;
            int t = q0 + rl;
            uint32_t qv = 0;
            if (t < SEQ) {
                __half2 q2 = *(const __half2*)(base + (size_t)t * (3 * DMODEL) + 2 * p);
                float2 qf = __half22float2(q2);
                __half2 qs = __floats2half2_rn(qf.x * 0.125f, qf.y * 0.125f);
                qv = *(uint32_t*)&qs;
            }
            *(uint32_t*)(Qs + rl * LDQK + 2 * p) = qv;
        }
        __syncthreads();

        // S = Qchunk @ K^T : warp tile 32x56, fragments via ldmatrix
        float c[2][7][4];
#pragma unroll
        for (int mi = 0; mi < 2; mi++)
#pragma unroll
            for (int ni = 0; ni < 7; ni++)
#pragma unroll
                for (int k = 0; k < 4; k++) c[mi][ni][k] = 0.0f;
#pragma unroll
        for (int ks = 0; ks < 4; ks++) {
            uint32_t kk0 = ks * 16;
            uint32_t a[2][4], bf[7][2];
#pragma unroll
            for (int mi = 0; mi < 2; mi++)
                LDSM_X4(a[mi][0], a[mi][1], a[mi][2], a[mi][3],
                        qbase + (((uint32_t)(wm * 32 + mi * 16) + aRowOff) * LDQK + kk0 + aColOff) * 2);
#pragma unroll
            for (int ni = 0; ni < 7; ni++)
                LDSM_X2(bf[ni][0], bf[ni][1],
                        kbase + (((uint32_t)(wn * 56 + ni * 8 + lr)) * LDQK + kk0 + bColOff) * 2);
#pragma unroll
            for (int mi = 0; mi < 2; mi++)
#pragma unroll
                for (int ni = 0; ni < 7; ni++)
                    mma_f16f32(c[mi][ni][0], c[mi][ni][1], c[mi][ni][2], c[mi][ni][3],
                               a[mi][0], a[mi][1], a[mi][2], a[mi][3], bf[ni][0], bf[ni][1]);
        }

        // mask padded key columns
#pragma unroll
        for (int ni = 0; ni < 7; ni++) {
            int col = wn * 56 + ni * 8 + 2 * tig;
            if (col >= SEQ) { c[0][ni][0] = c[0][ni][2] = c[1][ni][0] = c[1][ni][2] = -1e30f; }
            if (col + 1 >= SEQ) { c[0][ni][1] = c[0][ni][3] = c[1][ni][1] = c[1][ni][3] = -1e30f; }
        }

        // row max partials
#pragma unroll
        for (int mi = 0; mi < 2; mi++) {
            float m0 = -1e30f, m1 = -1e30f;
#pragma unroll
            for (int ni = 0; ni < 7; ni++) {
                m0 = fmaxf(m0, fmaxf(c[mi][ni][0], c[mi][ni][1]));
                m1 = fmaxf(m1, fmaxf(c[mi][ni][2], c[mi][ni][3]));
            }
#pragma unroll
            for (int o = 1; o <= 2; o <<= 1) {
                m0 = fmaxf(m0, __shfl_xor_sync(0xffffffffu, m0, o));
                m1 = fmaxf(m1, __shfl_xor_sync(0xffffffffu, m1, o));
            }
            if (tig == 0) {
                int rr = wm * 32 + mi * 16 + gid;
                redA[rr * 4 + wn] = m0;
                redA[(rr + 8) * 4 + wn] = m1;
            }
        }
        __syncthreads();

        // exp + partial sums
#pragma unroll
        for (int mi = 0; mi < 2; mi++) {
            int rr = wm * 32 + mi * 16 + gid;
            float4 ra = *(const float4*)(redA + rr * 4);
            float4 rb = *(const float4*)(redA + (rr + 8) * 4);
            float m0 = fmaxf(fmaxf(ra.x, ra.y), fmaxf(ra.z, ra.w));
            float m1 = fmaxf(fmaxf(rb.x, rb.y), fmaxf(rb.z, rb.w));
            float s0 = 0.0f, s1 = 0.0f;
#pragma unroll
            for (int ni = 0; ni < 7; ni++) {
                float e0 = __expf(c[mi][ni][0] - m0);
                float e1 = __expf(c[mi][ni][1] - m0);
                float e2 = __expf(c[mi][ni][2] - m1);
                float e3 = __expf(c[mi][ni][3] - m1);
                c[mi][ni][0] = e0; c[mi][ni][1] = e1; c[mi][ni][2] = e2; c[mi][ni][3] = e3;
                s0 += e0 + e1; s1 += e2 + e3;
            }
#pragma unroll
            for (int o = 1; o <= 2; o <<= 1) {
                s0 += __shfl_xor_sync(0xffffffffu, s0, o);
                s1 += __shfl_xor_sync(0xffffffffu, s1, o);
            }
            if (tig == 0) {
                redB[rr * 4 + wn] = s0;
                redB[(rr + 8) * 4 + wn] = s1;
            }
        }
        __syncthreads();

        // normalize -> Pm fp16
#pragma unroll
        for (int mi = 0; mi < 2; mi++) {
            int rr = wm * 32 + mi * 16 + gid;
            float4 ra = *(const float4*)(redB + rr * 4);
            float4 rb = *(const float4*)(redB + (rr + 8) * 4);
            float i0 = 1.0f / (ra.x + ra.y + ra.z + ra.w);
            float i1 = 1.0f / (rb.x + rb.y + rb.z + rb.w);
#pragma unroll
            for (int ni = 0; ni < 7; ni++) {
                int col = wn * 56 + ni * 8 + 2 * tig;
                __half2 p0 = __floats2half2_rn(c[mi][ni][0] * i0, c[mi][ni][1] * i0);
                __half2 p1 = __floats2half2_rn(c[mi][ni][2] * i1, c[mi][ni][3] * i1);
                *(__half2*)(Pm + rr * LDV + col) = p0;
                *(__half2*)(Pm + (rr + 8) * LDV + col) = p1;
            }
        }
        __syncthreads();

        // O = P @ V^T : warp tile 32x16, k=224, P via ldmatrix.x4, V via ldmatrix.trans
        float o[2][2][4];
#pragma unroll
        for (int mi = 0; mi < 2; mi++)
#pragma unroll
            for (int ni = 0; ni < 2; ni++)
#pragma unroll
                for (int k = 0; k < 4; k++) o[mi][ni][k] = 0.0f;

        int trow = lr + ((lane >> 3) & 1) * 8;  // k-row within 16 for lanes 0..15
#pragma unroll
        for (int ks = 0; ks < 14; ks++) {
            uint32_t kk0 = ks * 16;
            uint32_t a[2][4], bf[2][2];
#pragma unroll
            for (int mi = 0; mi < 2; mi++)
                LDSM_X4(a[mi][0], a[mi][1], a[mi][2], a[mi][3],
                        pbase + (((uint32_t)(wm * 32 + mi * 16) + aRowOff) * LDV + kk0 + aColOff) * 2);
#pragma unroll
            for (int ni = 0; ni < 2; ni++) {
                int d0 = wn * 16 + ni * 8;
                uint32_t addr = vbase + ((kk0 + (uint32_t)trow) * LDQK + d0) * 2;
                LDSM_X2T(bf[ni][0], bf[ni][1], addr);
            }
#pragma unroll
            for (int mi = 0; mi < 2; mi++)
#pragma unroll
                for (int ni = 0; ni < 2; ni++)
                    mma_f16f32(o[mi][ni][0], o[mi][ni][1], o[mi][ni][2], o[mi][ni][3],
                               a[mi][0], a[mi][1], a[mi][2], a[mi][3], bf[ni][0], bf[ni][1]);
        }
#pragma unroll
        for (int mi = 0; mi < 2; mi++) {
#pragma unroll
            for (int half_ = 0; half_ < 2; half_++) {
                int q = q0 + wm * 32 + mi * 16 + gid + half_ * 8;
                if (q >= SEQ) continue;
#pragma unroll
                for (int ni = 0; ni < 2; ni++) {
                    int d = wn * 16 + ni * 8 + 2 * tig;
                    union { __half h[2]; uint32_t u; } P2;
                    P2.h[0] = __float2half_rn(o[mi][ni][half_ * 2 + 0]);
                    P2.h[1] = __float2half_rn(o[mi][ni][half_ * 2 + 1]);
                    *(uint32_t*)(yH + (size_t)(b * SEQ + q) * DMODEL + h * DHEAD + d) = P2.u;
                }
            }
        }
        __syncthreads();
    }
}

// ---- weight convert+transpose: 64x64 tiles, vectorized ----
__global__ __launch_bounds__(256) void wconv_kernel(const float* __restrict__ W,
                                                    __half* __restrict__ out,
                                                    int K, int N) {
    __shared__ float t[64][65];
    W   += (size_t)blockIdx.z * K * N;
    out += (size_t)blockIdx.z * N * K;
    int k0 = blockIdx.y * 64, n0 = blockIdx.x * 64;
    int tid = threadIdx.x;
#pragma unroll
    for (int i = 0; i < 4; i++) {
        int idx = tid + i * 256;
        int r = idx >> 4, c4 = (idx & 15) * 4;
        float4 v = *(const float4*)(W + (size_t)(k0 + r) * N + n0 + c4);
        t[r][c4 + 0] = v.x; t[r][c4 + 1] = v.y; t[r][c4 + 2] = v.z; t[r][c4 + 3] = v.w;
    }
    __syncthreads();
#pragma unroll
    for (int i = 0; i < 4; i++) {
        int idx = tid + i * 256;
        int n = idx >> 4, kq = (idx & 15) * 4;
        __half2 h01 = __floats2half2_rn(t[kq + 0][n], t[kq + 1][n]);
        __half2 h23 = __floats2half2_rn(t[kq + 2][n], t[kq + 3][n]);
        uint2 u;
        u.x = *(uint32_t*)&h01;
        u.y = *(uint32_t*)&h23;
        *(uint2*)(out + (size_t)(n0 + n) * K + k0 + kq) = u;
    }
}

// ---- patch extraction ----
__global__ __launch_bounds__(256) void patch_kernel(const float* __restrict__ img,
                                                    __half* __restrict__ out) {
    int idx = blockIdx.x * 256 + threadIdx.x;
    if (idx >= M_PAT * DMODEL) return;
    int i = idx % DMODEL, row = idx / DMODEL;
    int p = row % NTOK, b = row / NTOK;
    int c = i >> 8, rem = i & 255, iy = rem >> 4, ix = rem & 15;
    int py = p / 14, px = p % 14;
    float v = img[(((size_t)(b*3 + c) * 224) + py*16 + iy) * 224 + px*16 + ix];
    out[idx] = __float2half_rn(v);
}

// ---- embed ----
__global__ __launch_bounds__(256) void embed_kernel(const float* __restrict__ tok,
                                                    const float* __restrict__ v_class,
                                                    float* __restrict__ x) {
    int idx = blockIdx.x * 256 + threadIdx.x;
    if (idx >= M_ALL * DMODEL) return;
    int d = idx % DMODEL, r = idx / DMODEL;
    int s = r % SEQ, b = r / SEQ;
    float t = (s == 0) ? v_class[d] : tok[(size_t)(b * NTOK + s - 1) * DMODEL + d];
    float ang = (float)s * __expf((float)d * (-9.210340371976184f / (float)DMODEL));
    x[idx] = t + (((d & 1) == 0) ? sinf(ang) : cosf(ang));
}

// ---- LayerNorm: warp per row ----
__global__ __launch_bounds__(256) void ln_kernel(const float* __restrict__ x,
                                                 const float* __restrict__ gamma,
                                                 const float* __restrict__ beta,
                                                 __half* __restrict__ outH) {
    int warp = threadIdx.x >> 5, lane = threadIdx.x & 31;
    int row = blockIdx.x * 8 + warp;
    const float4* xr = (const float4*)(x + (size_t)row * DMODEL);
    float4 v[6];
    float sum = 0.0f;
#pragma unroll
    for (int j = 0; j < 6; j++) {
        v[j] = xr[lane + 32 * j];
        sum += v[j].x + v[j].y + v[j].z + v[j].w;
    }
#pragma unroll
    for (int o = 16; o > 0; o >>= 1) sum += __shfl_xor_sync(0xffffffffu, sum, o);
    float mean = sum * (1.0f / DMODEL);
    float var = 0.0f;
#pragma unroll
    for (int j = 0; j < 6; j++) {
        float a = v[j].x - mean, b = v[j].y - mean, c = v[j].z - mean, d = v[j].w - mean;
        var += a*a + b*b + c*c + d*d;
    }
#pragma unroll
    for (int o = 16; o > 0; o >>= 1) var += __shfl_xor_sync(0xffffffffu, var, o);
    float rstd = rsqrtf(var * (1.0f / DMODEL) + 1e-5f);

    const float4* gr = (const float4*)gamma;
    const float4* br = (const float4*)beta;
    uint2* orow = (uint2*)(outH + (size_t)row * DMODEL);
#pragma unroll
    for (int j = 0; j < 6; j++) {
        float4 g = gr[lane + 32 * j], bb = br[lane + 32 * j];
        float o0 = (v[j].x - mean) * rstd * g.x + bb.x;
        float o1 = (v[j].y - mean) * rstd * g.y + bb.y;
        float o2 = (v[j].z - mean) * rstd * g.z + bb.z;
        float o3 = (v[j].w - mean) * rstd * g.w + bb.w;
        __half2 h01 = __floats2half2_rn(o0, o1);
        __half2 h23 = __floats2half2_rn(o2, o3);
        uint2 u;
        u.x = *(uint32_t*)&h01;
        u.y = *(uint32_t*)&h23;
        orow[lane + 32 * j] = u;
    }
}

// ---- KAN head ----
__global__ __launch_bounds__(256) void head_kernel(const float* __restrict__ x,
                                                   const float* __restrict__ amp,
                                                   float* __restrict__ logits) {
    __shared__ float sines[4 * DMODEL];
    int b = blockIdx.x, tid = threadIdx.x;
    const float* xr = x + (size_t)b * SEQ * DMODEL;
    const float PI = 3.14159265358979323846f;
    for (int i = tid; i < DMODEL; i += 256) {
        float xv = xr[i], ph = (float)i * (PI / (float)DMODEL);
#pragma unroll
        for (int g = 0; g < 4; g++) sines[g*DMODEL + i] = sinf(xv * (float)(g+1) + ph);
    }
    __syncthreads();
    int warp = tid >> 5, lane = tid & 31;
    int o = blockIdx.y * 8 + warp;
    if (o < NOUT) {
        const float* ar = amp + (size_t)o * 4 * DMODEL;
        float acc = 0.0f;
        for (int i = lane; i < 4*DMODEL; i += 32) acc = fmaf(sines[i], ar[i], acc);
#pragma unroll
        for (int of = 16; of > 0; of >>= 1) acc += __shfl_xor_sync(0xffffffffu, acc, of);
        if (lane == 0) logits[(size_t)b*NOUT + o] = acc * (1.0f / 55.42562584220407f);
    }
}

// ---- softmax ----
__global__ __launch_bounds__(256) void softmax_kernel(const float* __restrict__ logits,
                                                      float* __restrict__ out) {
    int b = blockIdx.x, tid = threadIdx.x;
    const float* lr = logits + (size_t)b * NOUT;
    __shared__ float red[256];
    float m = -1e30f;
    for (int i = tid; i < NOUT; i += 256) m = fmaxf(m, lr[i]);
    red[tid] = m; __syncthreads();
    for (int o = 128; o > 0; o >>= 1) { if (tid < o) red[tid] = fmaxf(red[tid], red[tid+o]); __syncthreads(); }
    m = red[0]; __syncthreads();
    float s = 0.0f;
    for (int i = tid; i < NOUT; i += 256) s += expf(lr[i] - m);
    red[tid] = s; __syncthreads();
    for (int o = 128; o > 0; o >>= 1) { if (tid < o) red[tid] += red[tid+o]; __syncthreads(); }
    float inv = 1.0f / red[0];
    for (int i = tid; i < NOUT; i += 256) out[(size_t)b*NOUT + i] = expf(lr[i] - m) * inv;
}

// ---- launch ----
extern "C" void kernel_launch(void* const* d_in, const int* in_sizes, int n_in,
                              void* d_out, int out_size) {
    (void)in_sizes; (void)n_in; (void)out_size;
    const float* images    = (const float*)d_in[0];
    const float* v_class   = (const float*)d_in[1];
    const float* W_map     = (const float*)d_in[2];
    const float* b_map     = (const float*)d_in[3];
    const float* ln1_scale = (const float*)d_in[4];
    const float* ln1_bias  = (const float*)d_in[5];
    const float* Wqkv      = (const float*)d_in[6];
    const float* bqkv      = (const float*)d_in[7];
    const float* Wo        = (const float*)d_in[8];
    const float* bo        = (const float*)d_in[9];
    const float* ln2_scale = (const float*)d_in[10];
    const float* ln2_bias  = (const float*)d_in[11];
    const float* Wmlp1     = (const float*)d_in[12];
    const float* bmlp1     = (const float*)d_in[13];
    const float* Wmlp2     = (const float*)d_in[14];
    const float* bmlp2     = (const float*)d_in[15];
    const float* kan_amp   = (const float*)d_in[16];
    float* out = (float*)d_out;

    void *p0,*p1,*p2,*p3,*p4,*p5,*p6,*p7,*p8,*p9,*p10,*p11,*p12;
    cudaGetSymbolAddress(&p0, g_patch_h); cudaGetSymbolAddress(&p1, g_tok);
    cudaGetSymbolAddress(&p2, g_x);       cudaGetSymbolAddress(&p3, g_h_h);
    cudaGetSymbolAddress(&p4, g_qkv_h);   cudaGetSymbolAddress(&p5, g_y_h);
    cudaGetSymbolAddress(&p6, g_ff_h);    cudaGetSymbolAddress(&p7, g_logits);
    cudaGetSymbolAddress(&p8, g_wmap_t);  cudaGetSymbolAddress(&p9, g_wqkv_t);
    cudaGetSymbolAddress(&p10, g_wo_t);   cudaGetSymbolAddress(&p11, g_wm1_t);
    cudaGetSymbolAddress(&p12, g_wm2_t);
    __half* patch_h = (__half*)p0;
    float* tok = (float*)p1;
    float* x   = (float*)p2;
    __half* h_h = (__half*)p3;
    __half* qkv_h = (__half*)p4;
    __half* y_h = (__half*)p5;
    __half* ff_h = (__half*)p6;
    float* logits = (float*)p7;
    __half* wmap_t = (__half*)p8;
    __half* wqkv_t = (__half*)p9;
    __half* wo_t   = (__half*)p10;
    __half* wm1_t  = (__half*)p11;
    __half* wm2_t  = (__half*)p12;

    cudaFuncSetAttribute(attn_kernel, cudaFuncAttributeMaxDynamicSharedMemorySize, (int)ATTN_SMEM);
    cudaFuncSetAttribute(mma_gemm_kernel, cudaFuncAttributeMaxDynamicSharedMemorySize, GEMM_SMEM);

    wconv_kernel<<<dim3(DMODEL/64, DMODEL/64, 1), 256>>>(W_map, wmap_t, DMODEL, DMODEL);
    wconv_kernel<<<dim3(3*DMODEL/64, DMODEL/64, NBLK), 256>>>(Wqkv, wqkv_t, DMODEL, 3*DMODEL);
    wconv_kernel<<<dim3(DMODEL/64, DMODEL/64, NBLK), 256>>>(Wo, wo_t, DMODEL, DMODEL);
    wconv_kernel<<<dim3(FFDIM/64, DMODEL/64, NBLK), 256>>>(Wmlp1, wm1_t, DMODEL, FFDIM);
    wconv_kernel<<<dim3(DMODEL/64, FFDIM/64, NBLK), 256>>>(Wmlp2, wm2_t, FFDIM, DMODEL);

    patch_kernel<<<(M_PAT*DMODEL + 255)/256, 256>>>(images, patch_h);
    mma_gemm_kernel<<<dim3(DMODEL/128, M_PAT/128), 256, GEMM_SMEM>>>(
        patch_h, wmap_t, b_map, nullptr, tok, nullptr, M_PAT, DMODEL, DMODEL, 0);
    embed_kernel<<<(M_ALL*DMODEL + 255)/256, 256>>>(tok, v_class, x);

    for (int blk = 0; blk < NBLK; blk++) {
        ln_kernel<<<M_ALL/8, 256>>>(x, ln1_scale + (size_t)blk*DMODEL, ln1_bias + (size_t)blk*DMODEL, h_h);
        mma_gemm_kernel<<<dim3(3*DMODEL/128, MTILES), 256, GEMM_SMEM>>>(
            h_h, wqkv_t + (size_t)blk*3*DMODEL*DMODEL, bqkv + (size_t)blk*3*DMODEL,
            nullptr, nullptr, qkv_h, M_ALL, 3*DMODEL, DMODEL, 0);
        attn_kernel<<<dim3(NHEAD, BATCH), 256, ATTN_SMEM>>>(qkv_h, y_h);
        mma_gemm_kernel<<<dim3(DMODEL/128, MTILES), 256, GEMM_SMEM>>>(
            y_h, wo_t + (size_t)blk*DMODEL*DMODEL, bo + (size_t)blk*DMODEL,
            x, x, nullptr, M_ALL, DMODEL, DMODEL, 0);
        ln_kernel<<<M_ALL/8, 256>>>(x, ln2_scale + (size_t)blk*DMODEL, ln2_bias + (size_t)blk*DMODEL, h_h);
        mma_gemm_kernel<<<dim3(FFDIM/128, MTILES), 256, GEMM_SMEM>>>(
            h_h, wm1_t + (size_t)blk*FFDIM*DMODEL, bmlp1 + (size_t)blk*FFDIM,
            nullptr, nullptr, ff_h, M_ALL, FFDIM, DMODEL, 1);
        mma_gemm_kernel<<<dim3(DMODEL/128, MTILES), 256, GEMM_SMEM>>>(
            ff_h, wm2_t + (size_t)blk*DMODEL*FFDIM, bmlp2 + (size_t)blk*DMODEL,
            x, x, nullptr, M_ALL, DMODEL, FFDIM, 0);
    }

    head_kernel<<<dim3(BATCH, 125), 256>>>(x, kan_amp, logits);
    softmax_kernel<<<BATCH, 256>>>(logits, out);
}